// round 2
// baseline (speedup 1.0000x reference)
#include <cuda_runtime.h>
#include <math.h>

// Problem constants
#define B_   16
#define C_   512
#define R_   32
#define SP_  1024          // R*R
#define HN_  8
#define D_   128
// x is [16, 512, 96, 96]

// ---------------- scratch (static device arrays; no allocation) -------------
__device__ float g_qpool[B_*C_*SP_];        // flat [b][c*1024+sp]  (33.5 MB)
__device__ float g_kpool[B_*C_*SP_];
__device__ float g_vpool[B_*C_*SP_];        // Wv @ qpool + bv
__device__ float g_Qt[B_*HN_*D_*C_];        // [z=b*8+h][e*512 + c]
__device__ float g_Kt[B_*HN_*D_*C_];
__device__ float g_S [B_*HN_*C_*C_];        // [z][c*512 + e]       (134 MB)
__device__ float g_rowscale[B_*HN_*C_];
__device__ float g_attnT[B_*HN_*D_*C_];     // [z][d*512 + c]

// ---------------- kernel 1: fused avg+max 3x3 pooling ----------------------
// one block per (b,c) plane (8192 blocks); stage 96x96 plane in smem
__global__ void __launch_bounds__(256) pool_kernel(const float* __restrict__ x) {
    __shared__ float tile[9216];
    const float4* s4 = reinterpret_cast<const float4*>(x + (size_t)blockIdx.x * 9216);
    float4* t4 = reinterpret_cast<float4*>(tile);
    #pragma unroll
    for (int i = 0; i < 9; i++)
        t4[threadIdx.x + i*256] = s4[threadIdx.x + i*256];
    __syncthreads();
    size_t base = (size_t)blockIdx.x * 1024;
    #pragma unroll
    for (int it = 0; it < 4; it++) {
        int sp = threadIdx.x + it*256;
        int r1 = sp >> 5, r2 = sp & 31;
        const float* p = &tile[r1*3*96 + r2*3];
        float s = 0.f, m = -3.4e38f;
        #pragma unroll
        for (int i = 0; i < 3; i++)
            #pragma unroll
            for (int j = 0; j < 3; j++) {
                float v = p[i*96 + j];
                s += v;
                m = fmaxf(m, v);
            }
        g_qpool[base + sp] = s * (1.f/9.f);
        g_kpool[base + sp] = m;
    }
}

// ---------------- generic 128x128x8 tiled SGEMM ----------------------------
// C[z] = A[z] * B[z] (+ bias over M).  Layouts:
//   A_KM=false : A[m*K + k]     A_KM=true : A[k*M + m]
//   B_NK=false : B[k*N + n]     B_NK=true : B[n*K + k]
// offsets: A += (z % aMod)*aStride; B += z*bStride; C += z*cStride;
//          bias index = (z % biasMod)*biasStride + m
template<bool A_KM, bool B_NK, bool HAS_BIAS>
__global__ void __launch_bounds__(256) gemm128_kernel(
    const float* __restrict__ A, const float* __restrict__ B,
    const float* __restrict__ bias, float* __restrict__ C,
    int M, int N, int K,
    int aMod, long aStride, long bStride, long cStride,
    int biasMod, int biasStride)
{
    const int z = blockIdx.z;
    A += (size_t)(z % aMod) * aStride;
    B += (size_t)z * bStride;
    C += (size_t)z * cStride;

    __shared__ float As[8][128];
    __shared__ float Bs[8][128];

    const int bm = blockIdx.y * 128;
    const int bn = blockIdx.x * 128;
    const int tid  = threadIdx.x;
    const int trow = tid >> 4;     // 0..15
    const int tcol = tid & 15;     // 0..15

    float acc[8][8];
    #pragma unroll
    for (int i = 0; i < 8; i++)
        #pragma unroll
        for (int j = 0; j < 8; j++) acc[i][j] = 0.f;

    for (int k0 = 0; k0 < K; k0 += 8) {
        if (A_KM) {
            int k = tid >> 7, m = tid & 127;
            #pragma unroll
            for (int r = 0; r < 4; r++)
                As[k + 2*r][m] = A[(size_t)(k0 + k + 2*r) * M + (bm + m)];
        } else {
            int m = tid >> 1, kk = (tid & 1) << 2;
            float4 v = *reinterpret_cast<const float4*>(&A[(size_t)(bm + m) * K + k0 + kk]);
            As[kk+0][m] = v.x; As[kk+1][m] = v.y; As[kk+2][m] = v.z; As[kk+3][m] = v.w;
        }
        if (B_NK) {
            int n = tid >> 1, kk = (tid & 1) << 2;
            float4 v = *reinterpret_cast<const float4*>(&B[(size_t)(bn + n) * K + k0 + kk]);
            Bs[kk+0][n] = v.x; Bs[kk+1][n] = v.y; Bs[kk+2][n] = v.z; Bs[kk+3][n] = v.w;
        } else {
            int k = tid >> 7, n = tid & 127;
            #pragma unroll
            for (int r = 0; r < 4; r++)
                Bs[k + 2*r][n] = B[(size_t)(k0 + k + 2*r) * N + (bn + n)];
        }
        __syncthreads();
        #pragma unroll
        for (int k = 0; k < 8; k++) {
            float a[8], b[8];
            *reinterpret_cast<float4*>(&a[0]) = *reinterpret_cast<float4*>(&As[k][trow*8]);
            *reinterpret_cast<float4*>(&a[4]) = *reinterpret_cast<float4*>(&As[k][trow*8+4]);
            *reinterpret_cast<float4*>(&b[0]) = *reinterpret_cast<float4*>(&Bs[k][tcol*8]);
            *reinterpret_cast<float4*>(&b[4]) = *reinterpret_cast<float4*>(&Bs[k][tcol*8+4]);
            #pragma unroll
            for (int i = 0; i < 8; i++)
                #pragma unroll
                for (int j = 0; j < 8; j++)
                    acc[i][j] = fmaf(a[i], b[j], acc[i][j]);
        }
        __syncthreads();
    }

    #pragma unroll
    for (int i = 0; i < 8; i++) {
        int m = bm + trow*8 + i;
        float bvv = HAS_BIAS ? bias[(size_t)(z % biasMod) * biasStride + m] : 0.f;
        float* crow = &C[(size_t)m * N + bn + tcol*8];
        float4 v0 = make_float4(acc[i][0]+bvv, acc[i][1]+bvv, acc[i][2]+bvv, acc[i][3]+bvv);
        float4 v1 = make_float4(acc[i][4]+bvv, acc[i][5]+bvv, acc[i][6]+bvv, acc[i][7]+bvv);
        *reinterpret_cast<float4*>(&crow[0]) = v0;
        *reinterpret_cast<float4*>(&crow[4]) = v1;
    }
}

// ---------------- kernel: row means -> p gate -> row scale ------------------
// one block per z=(b,h); 512 threads
__global__ void __launch_bounds__(512) pgate_kernel(const float* __restrict__ Wp,
                                                    const float* __restrict__ bp) {
    const int z = blockIdx.x;
    const float* S = g_S + (size_t)z * 262144;
    __shared__ float msh[512];
    const int tid = threadIdx.x;
    const int warp = tid >> 5, lane = tid & 31;

    // row means (16 warps x 32 rows each)
    for (int j = warp; j < 512; j += 16) {
        const float* row = S + (size_t)j * 512;
        float s = 0.f;
        #pragma unroll 4
        for (int e = lane; e < 512; e += 32) s += row[e];
        #pragma unroll
        for (int o = 16; o; o >>= 1) s += __shfl_xor_sync(0xffffffffu, s, o);
        if (lane == 0) msh[j] = s * (1.f/512.f);
    }
    __syncthreads();

    // p[i] = sigmoid( sum_j m[j] * Wp[i,j] + bp[i] )
    float accv = bp[tid];
    const float* wrow = Wp + (size_t)tid * 512;
    #pragma unroll 4
    for (int j = 0; j < 512; j++) accv = fmaf(msh[j], wrow[j], accv);
    float p = 1.f / (1.f + expf(-accv));
    // scale = D^{-(0.5+p)} = 2^{-7(0.5+p)}
    g_rowscale[(size_t)z * 512 + tid] = exp2f(-7.f * (0.5f + p));
}

// ---------------- kernel: row-wise scaled softmax (in place) ----------------
// one block per row (65536 blocks x 128 threads, 4 elems/thread)
__global__ void __launch_bounds__(128) softmax_kernel() {
    const size_t row = blockIdx.x;
    float* S = g_S + row * 512;
    const float scale = g_rowscale[row];
    const int tid = threadIdx.x;

    float4 v = reinterpret_cast<float4*>(S)[tid];
    v.x *= scale; v.y *= scale; v.z *= scale; v.w *= scale;

    __shared__ float red[4], red2[4];
    float mx = fmaxf(fmaxf(v.x, v.y), fmaxf(v.z, v.w));
    #pragma unroll
    for (int o = 16; o; o >>= 1) mx = fmaxf(mx, __shfl_xor_sync(0xffffffffu, mx, o));
    if ((tid & 31) == 0) red[tid >> 5] = mx;
    __syncthreads();
    mx = fmaxf(fmaxf(red[0], red[1]), fmaxf(red[2], red[3]));

    float e0 = expf(v.x - mx), e1 = expf(v.y - mx), e2 = expf(v.z - mx), e3 = expf(v.w - mx);
    float s = e0 + e1 + e2 + e3;
    #pragma unroll
    for (int o = 16; o; o >>= 1) s += __shfl_xor_sync(0xffffffffu, s, o);
    if ((tid & 31) == 0) red2[tid >> 5] = s;
    __syncthreads();
    s = red2[0] + red2[1] + red2[2] + red2[3];

    float inv = 1.f / s;
    float4 o4 = make_float4(e0*inv, e1*inv, e2*inv, e3*inv);
    reinterpret_cast<float4*>(S)[tid] = o4;
}

// ---------------- kernel: residual + scaled attention (elementwise) ---------
__global__ void __launch_bounds__(256) final_kernel(const int* __restrict__ wptr,
                                                    float* __restrict__ out) {
    const float ws = 1.f + (float)wptr[0];
    size_t i = (size_t)blockIdx.x * 256 + threadIdx.x;
    float4 a = reinterpret_cast<const float4*>(g_qpool)[i];
    float4 b = reinterpret_cast<const float4*>(g_attnT)[i];
    float4 o = make_float4(a.x + b.x*ws, a.y + b.y*ws, a.z + b.z*ws, a.w + b.w*ws);
    reinterpret_cast<float4*>(out)[i] = o;
}

// ---------------- launch ----------------------------------------------------
extern "C" void kernel_launch(void* const* d_in, const int* in_sizes, int n_in,
                              void* d_out, int out_size) {
    const float* x   = (const float*)d_in[0];
    const float* Wqk = (const float*)d_in[1];
    const float* bqk = (const float*)d_in[2];
    const float* Wp  = (const float*)d_in[3];
    const float* bp  = (const float*)d_in[4];
    const float* Wv  = (const float*)d_in[5];
    const float* bv  = (const float*)d_in[6];
    const int*   wgt = (const int*)d_in[7];
    float* out = (float*)d_out;

    float *qpool, *kpool, *vpool, *Qt, *Kt, *S, *attnT;
    cudaGetSymbolAddress((void**)&qpool, g_qpool);
    cudaGetSymbolAddress((void**)&kpool, g_kpool);
    cudaGetSymbolAddress((void**)&vpool, g_vpool);
    cudaGetSymbolAddress((void**)&Qt,    g_Qt);
    cudaGetSymbolAddress((void**)&Kt,    g_Kt);
    cudaGetSymbolAddress((void**)&S,     g_S);
    cudaGetSymbolAddress((void**)&attnT, g_attnT);

    // 1) fused avg/max pooling: x -> qpool, kpool
    pool_kernel<<<8192, 256>>>(x);

    // 2) vpool[b] = Wv(512x512) @ qpool[b](512x1024) + bv   (1x1 conv & avgpool commute)
    gemm128_kernel<false,false,true><<<dim3(8,4,16), 256>>>(
        Wv, qpool, bv, vpool, 512, 1024, 512,
        1, 0, 524288, 524288, 1, 0);

    // 3) Qt[z](128x512) = Wqk[h] @ qpool_block[z] + bqk[h]   (z = b*8+h)
    gemm128_kernel<false,false,true><<<dim3(4,1,128), 256>>>(
        Wqk, qpool, bqk, Qt, 128, 512, 128,
        8, 16384, 65536, 65536, 8, 128);
    //    Kt from kpool
    gemm128_kernel<false,false,true><<<dim3(4,1,128), 256>>>(
        Wqk, kpool, bqk, Kt, 128, 512, 128,
        8, 16384, 65536, 65536, 8, 128);

    // 4) S[z](512x512) = Qt[z]^T @ Kt[z]
    gemm128_kernel<true,false,false><<<dim3(4,4,128), 256>>>(
        Qt, Kt, nullptr, S, 512, 512, 128,
        1<<30, 65536, 65536, 262144, 1, 0);

    // 5) row means -> sigmoid gate -> per-row scale
    pgate_kernel<<<128, 512>>>(Wp, bp);

    // 6) scaled softmax over keys, in place
    softmax_kernel<<<65536, 128>>>();

    // 7) attnT[z](128x512) = Vblock[z](128x512) @ w[z]^T
    gemm128_kernel<false,true,false><<<dim3(4,1,128), 256>>>(
        vpool, S, nullptr, attnT, 128, 512, 512,
        1<<30, 65536, 262144, 65536, 1, 0);

    // 8) out.flat = qpool.flat + attnT.flat * (1 + weight)
    final_kernel<<<8192, 256>>>(wgt, out);
}

// round 3
// speedup vs baseline: 2.0419x; 2.0419x over previous
#include <cuda_runtime.h>
#include <math.h>
#include <stdint.h>

// Problem constants
#define B_   16
#define C_   512
#define SP_  1024          // R*R
#define HN_  8
#define D_   128
// x is [16, 512, 96, 96]

// ---------------- scratch (static device arrays; no allocation) -------------
__device__ float g_qpool[B_*C_*SP_];        // flat [b][c*1024+sp]
__device__ float g_kpool[B_*C_*SP_];
__device__ float g_vpool[B_*C_*SP_];
__device__ float g_Qt[B_*HN_*D_*C_];        // [z=b*8+h][e*512 + c]
__device__ float g_Kt[B_*HN_*D_*C_];
__device__ float g_S [B_*HN_*C_*C_];        // [z][c*512 + e]
__device__ float g_rowsum[B_*HN_*C_];       // fused row sums of S
__device__ float g_rowscale[B_*HN_*C_];

// ---------------- tf32 helpers ----------------------------------------------
__device__ __forceinline__ uint32_t f2tf32(float x) {
    uint32_t r; asm("cvt.rna.tf32.f32 %0, %1;" : "=r"(r) : "f"(x)); return r;
}
__device__ __forceinline__ void mma_tf32(float* d, const uint32_t* a, const uint32_t* b) {
    asm volatile("mma.sync.aligned.m16n8k8.row.col.f32.tf32.tf32.f32 "
        "{%0,%1,%2,%3}, {%4,%5,%6,%7}, {%8,%9}, {%0,%1,%2,%3};"
        : "+f"(d[0]), "+f"(d[1]), "+f"(d[2]), "+f"(d[3])
        : "r"(a[0]), "r"(a[1]), "r"(a[2]), "r"(a[3]), "r"(b[0]), "r"(b[1]));
}

// ---------------- kernel 1: fused avg+max 3x3 pooling ----------------------
__global__ void __launch_bounds__(256) pool_kernel(const float* __restrict__ x) {
    __shared__ float tile[9216];
    const float4* s4 = reinterpret_cast<const float4*>(x + (size_t)blockIdx.x * 9216);
    float4* t4 = reinterpret_cast<float4*>(tile);
    #pragma unroll
    for (int i = 0; i < 9; i++)
        t4[threadIdx.x + i*256] = s4[threadIdx.x + i*256];
    __syncthreads();
    size_t base = (size_t)blockIdx.x * 1024;
    #pragma unroll
    for (int it = 0; it < 4; it++) {
        int sp = threadIdx.x + it*256;
        int r1 = sp >> 5, r2 = sp & 31;
        const float* p = &tile[r1*3*96 + r2*3];
        float s = 0.f, m = -3.4e38f;
        #pragma unroll
        for (int i = 0; i < 3; i++)
            #pragma unroll
            for (int j = 0; j < 3; j++) {
                float v = p[i*96 + j];
                s += v;
                m = fmaxf(m, v);
            }
        g_qpool[base + sp] = s * (1.f/9.f);
        g_kpool[base + sp] = m;
    }
}

__global__ void zero_rowsum_kernel() {
    g_rowsum[blockIdx.x * 256 + threadIdx.x] = 0.f;
}

// ---------------- tf32 tensor-core GEMM, 128x128 tile, K-chunk 16 -----------
// C[z](M x N) = A[z] * B[z] (+ bias over M)
//   A_KM=false : A[m*K+k]   A_KM=true : A[k*M+m]
//   B_NK=false : B[k*N+n]   B_NK=true : B[n*K+k]
// ROWSUM: atomically accumulate row sums of C into rowsum[z*M + m]
// FUSE_OUT: C = resid + acc * (1 + *wptr)
#define LDP 136
template<bool A_KM, bool B_NK, bool HAS_BIAS, bool ROWSUM, bool FUSE_OUT>
__global__ void __launch_bounds__(256) mm_tf32(
    const float* __restrict__ A, const float* __restrict__ Bm,
    const float* __restrict__ bias, float* __restrict__ Cc,
    int M, int N, int K,
    int aMod, long long aStride, long long bStride, long long cStride,
    int biasMod, int biasStride,
    float* __restrict__ rowsum,
    const float* __restrict__ resid, const int* __restrict__ wptr)
{
    __shared__ uint32_t As[2][16][LDP];
    __shared__ uint32_t Bs[2][16][LDP];

    const int z = blockIdx.z;
    A  += (size_t)(z % aMod) * aStride;
    Bm += (size_t)z * bStride;
    Cc += (size_t)z * cStride;
    if (ROWSUM)   rowsum += (size_t)z * M;
    if (FUSE_OUT) resid  += (size_t)z * cStride;

    const int bm = blockIdx.y * 128;
    const int bn = blockIdx.x * 128;
    const int tid  = threadIdx.x;
    const int lane = tid & 31;
    const int warp = tid >> 5;
    const int wm = warp >> 1;       // 0..3  (M direction)
    const int wn = warp & 1;        // 0..1  (N direction)
    const int qr = lane >> 2;       // 0..7
    const int cq = lane & 3;        // 0..3

    float acc[2][8][4];
    #pragma unroll
    for (int i = 0; i < 2; i++)
        #pragma unroll
        for (int j = 0; j < 8; j++)
            #pragma unroll
            for (int k = 0; k < 4; k++) acc[i][j][k] = 0.f;

    float pa[8], pb[8];

    // ---- global -> register prefetch ----
    auto loadA = [&](int k0) {
        if (A_KM) {
            int kk = tid >> 5, m4 = (tid & 31) << 2;
            *(float4*)&pa[0] = *(const float4*)&A[(size_t)(k0+kk)  *M + bm + m4];
            *(float4*)&pa[4] = *(const float4*)&A[(size_t)(k0+kk+8)*M + bm + m4];
        } else {
            int m = tid >> 2, kq4 = (tid & 3) << 2;
            *(float4*)&pa[0] = *(const float4*)&A[(size_t)(bm+m)   *K + k0 + kq4];
            *(float4*)&pa[4] = *(const float4*)&A[(size_t)(bm+m+64)*K + k0 + kq4];
        }
    };
    auto loadB = [&](int k0) {
        if (B_NK) {
            int n = tid >> 2, kq4 = (tid & 3) << 2;
            *(float4*)&pb[0] = *(const float4*)&Bm[(size_t)(bn+n)   *K + k0 + kq4];
            *(float4*)&pb[4] = *(const float4*)&Bm[(size_t)(bn+n+64)*K + k0 + kq4];
        } else {
            int kk = tid >> 5, n4 = (tid & 31) << 2;
            *(float4*)&pb[0] = *(const float4*)&Bm[(size_t)(k0+kk)  *N + bn + n4];
            *(float4*)&pb[4] = *(const float4*)&Bm[(size_t)(k0+kk+8)*N + bn + n4];
        }
    };
    // ---- register -> smem (tf32 converted) ----
    auto storeA = [&](int buf) {
        if (A_KM) {
            int kk = tid >> 5, m4 = (tid & 31) << 2;
            uint32_t* p0 = &As[buf][kk][m4];
            uint32_t* p1 = &As[buf][kk+8][m4];
            #pragma unroll
            for (int j = 0; j < 4; j++) { p0[j] = f2tf32(pa[j]); p1[j] = f2tf32(pa[4+j]); }
        } else {
            int m = tid >> 2, kq4 = (tid & 3) << 2;
            #pragma unroll
            for (int j = 0; j < 4; j++) {
                As[buf][kq4+j][m]    = f2tf32(pa[j]);
                As[buf][kq4+j][m+64] = f2tf32(pa[4+j]);
            }
        }
    };
    auto storeB = [&](int buf) {
        if (B_NK) {
            int n = tid >> 2, kq4 = (tid & 3) << 2;
            #pragma unroll
            for (int j = 0; j < 4; j++) {
                Bs[buf][kq4+j][n]    = f2tf32(pb[j]);
                Bs[buf][kq4+j][n+64] = f2tf32(pb[4+j]);
            }
        } else {
            int kk = tid >> 5, n4 = (tid & 31) << 2;
            uint32_t* p0 = &Bs[buf][kk][n4];
            uint32_t* p1 = &Bs[buf][kk+8][n4];
            #pragma unroll
            for (int j = 0; j < 4; j++) { p0[j] = f2tf32(pb[j]); p1[j] = f2tf32(pb[4+j]); }
        }
    };
    auto compute = [&](int buf) {
        #pragma unroll
        for (int kk = 0; kk < 16; kk += 8) {
            uint32_t af[2][4], bf[8][2];
            #pragma unroll
            for (int mt = 0; mt < 2; mt++) {
                int mb = wm*32 + mt*16 + qr;
                af[mt][0] = As[buf][kk+cq  ][mb];
                af[mt][1] = As[buf][kk+cq  ][mb+8];
                af[mt][2] = As[buf][kk+cq+4][mb];
                af[mt][3] = As[buf][kk+cq+4][mb+8];
            }
            #pragma unroll
            for (int nt = 0; nt < 8; nt++) {
                int nb = wn*64 + nt*8 + qr;
                bf[nt][0] = Bs[buf][kk+cq  ][nb];
                bf[nt][1] = Bs[buf][kk+cq+4][nb];
            }
            #pragma unroll
            for (int mt = 0; mt < 2; mt++)
                #pragma unroll
                for (int nt = 0; nt < 8; nt++)
                    mma_tf32(acc[mt][nt], af[mt], bf[nt]);
        }
    };

    // ---- pipelined main loop ----
    const int nT = K >> 4;
    loadA(0); loadB(0);
    storeA(0); storeB(0);
    __syncthreads();
    for (int t = 0; t < nT; t++) {
        int buf = t & 1;
        if (t + 1 < nT) { loadA((t+1) << 4); loadB((t+1) << 4); }
        compute(buf);
        if (t + 1 < nT) { storeA(buf ^ 1); storeB(buf ^ 1); }
        __syncthreads();
    }

    // ---- epilogue ----
    const float ws = FUSE_OUT ? (1.f + (float)wptr[0]) : 0.f;
    #pragma unroll
    for (int mt = 0; mt < 2; mt++) {
        int row0 = bm + wm*32 + mt*16 + qr;
        float b0 = 0.f, b1 = 0.f;
        if (HAS_BIAS) {
            const float* bptr = bias + (size_t)(z % biasMod) * biasStride;
            b0 = bptr[row0]; b1 = bptr[row0 + 8];
        }
        float s0 = 0.f, s1 = 0.f;
        #pragma unroll
        for (int nt = 0; nt < 8; nt++) {
            int col = bn + wn*64 + nt*8 + cq*2;
            float* d = acc[mt][nt];
            if (FUSE_OUT) {
                float2 rv0 = *(const float2*)&resid[(size_t)row0    *N + col];
                float2 rv1 = *(const float2*)&resid[(size_t)(row0+8)*N + col];
                *(float2*)&Cc[(size_t)row0    *N + col] = make_float2(rv0.x + d[0]*ws, rv0.y + d[1]*ws);
                *(float2*)&Cc[(size_t)(row0+8)*N + col] = make_float2(rv1.x + d[2]*ws, rv1.y + d[3]*ws);
            } else {
                *(float2*)&Cc[(size_t)row0    *N + col] = make_float2(d[0] + b0, d[1] + b0);
                *(float2*)&Cc[(size_t)(row0+8)*N + col] = make_float2(d[2] + b1, d[3] + b1);
            }
            if (ROWSUM) { s0 += d[0] + d[1]; s1 += d[2] + d[3]; }
        }
        if (ROWSUM) {
            s0 += __shfl_xor_sync(0xffffffffu, s0, 1);
            s0 += __shfl_xor_sync(0xffffffffu, s0, 2);
            s1 += __shfl_xor_sync(0xffffffffu, s1, 1);
            s1 += __shfl_xor_sync(0xffffffffu, s1, 2);
            if (cq == 0) {
                atomicAdd(&rowsum[row0],     s0);
                atomicAdd(&rowsum[row0 + 8], s1);
            }
        }
    }
}

// ---------------- kernel: rowsums -> p gate -> row scale --------------------
__global__ void __launch_bounds__(512) pgate_kernel(const float* __restrict__ Wp,
                                                    const float* __restrict__ bp) {
    const int z = blockIdx.x;
    __shared__ float msh[512];
    const int tid = threadIdx.x;
    msh[tid] = g_rowsum[(size_t)z * 512 + tid] * (1.f/512.f);
    __syncthreads();

    float accv = bp[tid];
    const float* wrow = Wp + (size_t)tid * 512;
    #pragma unroll 4
    for (int j = 0; j < 512; j++) accv = fmaf(msh[j], wrow[j], accv);
    float p = 1.f / (1.f + expf(-accv));
    g_rowscale[(size_t)z * 512 + tid] = exp2f(-7.f * (0.5f + p));   // D^{-(0.5+p)}
}

// ---------------- kernel: row-wise scaled softmax (in place) ----------------
__global__ void __launch_bounds__(128) softmax_kernel() {
    const size_t row = blockIdx.x;
    float* S = g_S + row * 512;
    const float scale = g_rowscale[row];
    const int tid = threadIdx.x;

    float4 v = reinterpret_cast<float4*>(S)[tid];
    v.x *= scale; v.y *= scale; v.z *= scale; v.w *= scale;

    __shared__ float red[4], red2[4];
    float mx = fmaxf(fmaxf(v.x, v.y), fmaxf(v.z, v.w));
    #pragma unroll
    for (int o = 16; o; o >>= 1) mx = fmaxf(mx, __shfl_xor_sync(0xffffffffu, mx, o));
    if ((tid & 31) == 0) red[tid >> 5] = mx;
    __syncthreads();
    mx = fmaxf(fmaxf(red[0], red[1]), fmaxf(red[2], red[3]));

    float e0 = expf(v.x - mx), e1 = expf(v.y - mx), e2 = expf(v.z - mx), e3 = expf(v.w - mx);
    float s = e0 + e1 + e2 + e3;
    #pragma unroll
    for (int o = 16; o; o >>= 1) s += __shfl_xor_sync(0xffffffffu, s, o);
    if ((tid & 31) == 0) red2[tid >> 5] = s;
    __syncthreads();
    s = red2[0] + red2[1] + red2[2] + red2[3];

    float inv = 1.f / s;
    reinterpret_cast<float4*>(S)[tid] = make_float4(e0*inv, e1*inv, e2*inv, e3*inv);
}

// ---------------- launch ----------------------------------------------------
extern "C" void kernel_launch(void* const* d_in, const int* in_sizes, int n_in,
                              void* d_out, int out_size) {
    const float* x   = (const float*)d_in[0];
    const float* Wqk = (const float*)d_in[1];
    const float* bqk = (const float*)d_in[2];
    const float* Wp  = (const float*)d_in[3];
    const float* bp  = (const float*)d_in[4];
    const float* Wv  = (const float*)d_in[5];
    const float* bv  = (const float*)d_in[6];
    const int*   wgt = (const int*)d_in[7];
    float* out = (float*)d_out;

    float *qpool, *kpool, *vpool, *Qt, *Kt, *S, *rowsum;
    cudaGetSymbolAddress((void**)&qpool,  g_qpool);
    cudaGetSymbolAddress((void**)&kpool,  g_kpool);
    cudaGetSymbolAddress((void**)&vpool,  g_vpool);
    cudaGetSymbolAddress((void**)&Qt,     g_Qt);
    cudaGetSymbolAddress((void**)&Kt,     g_Kt);
    cudaGetSymbolAddress((void**)&S,      g_S);
    cudaGetSymbolAddress((void**)&rowsum, g_rowsum);

    // 1) fused avg/max pooling: x -> qpool, kpool
    pool_kernel<<<8192, 256>>>(x);
    zero_rowsum_kernel<<<256, 256>>>();

    // 2) vpool[b] = Wv @ qpool[b] + bv   (1x1 conv & avgpool commute)
    mm_tf32<false,false,true,false,false><<<dim3(8,4,16), 256>>>(
        Wv, qpool, bv, vpool, 512, 1024, 512,
        1, 0, 524288, 524288, 1, 0, nullptr, nullptr, nullptr);

    // 3) Qt[z] = Wqk[h] @ qpool_block[z] + bqk[h];  Kt from kpool
    mm_tf32<false,false,true,false,false><<<dim3(4,1,128), 256>>>(
        Wqk, qpool, bqk, Qt, 128, 512, 128,
        8, 16384, 65536, 65536, 8, 128, nullptr, nullptr, nullptr);
    mm_tf32<false,false,true,false,false><<<dim3(4,1,128), 256>>>(
        Wqk, kpool, bqk, Kt, 128, 512, 128,
        8, 16384, 65536, 65536, 8, 128, nullptr, nullptr, nullptr);

    // 4) S[z] = Qt[z]^T @ Kt[z]  (+ fused row-sum accumulation)
    mm_tf32<true,false,false,true,false><<<dim3(4,4,128), 256>>>(
        Qt, Kt, nullptr, S, 512, 512, 128,
        1<<30, 65536, 65536, 262144, 1, 0, rowsum, nullptr, nullptr);

    // 5) sigmoid gate -> per-row scale (reads fused row sums)
    pgate_kernel<<<128, 512>>>(Wp, bp);

    // 6) scaled softmax over keys, in place
    softmax_kernel<<<65536, 128>>>();

    // 7) out[z] = qpool[z] + (Vblock[z] @ w[z]^T) * (1 + weight)   (fused final)
    mm_tf32<false,true,false,false,true><<<dim3(4,1,128), 256>>>(
        vpool, S, nullptr, out, 128, 512, 512,
        1<<30, 65536, 262144, 65536, 1, 0, nullptr, qpool, wgt);
}

// round 6
// speedup vs baseline: 2.1438x; 1.0499x over previous
#include <cuda_runtime.h>
#include <math.h>
#include <stdint.h>

// Problem constants
#define B_   16
#define C_   512
#define SP_  1024          // R*R
#define HN_  8
#define D_   128
#define NEG_INF -3.4e38f
// x is [16, 512, 96, 96]

// ---------------- scratch (static device arrays; no allocation) -------------
__device__ float g_qpool[B_*C_*SP_];        // flat [b][c*1024+sp]
__device__ float g_kpool[B_*C_*SP_];
__device__ float g_vpool[B_*C_*SP_];
__device__ float g_Qt[B_*HN_*D_*C_];        // [z=b*8+h][e*512 + c]
__device__ float g_Kt[B_*HN_*D_*C_];
__device__ float g_S [B_*HN_*C_*C_];        // scaled scores [z][c*512 + e]
__device__ float g_kmean[B_*HN_*D_];        // row sums of Kt (over c)
__device__ float g_rowmax[B_*HN_*C_];       // max of scaled scores per (z,c)
__device__ float g_rowscale[B_*HN_*C_];

// ---------------- helpers ----------------------------------------------------
__device__ __forceinline__ uint32_t f2tf32(float x) {
    uint32_t r; asm("cvt.rna.tf32.f32 %0, %1;" : "=r"(r) : "f"(x)); return r;
}
__device__ __forceinline__ void mma_tf32(float* d, const uint32_t* a, const uint32_t* b) {
    asm volatile("mma.sync.aligned.m16n8k8.row.col.f32.tf32.tf32.f32 "
        "{%0,%1,%2,%3}, {%4,%5,%6,%7}, {%8,%9}, {%0,%1,%2,%3};"
        : "+f"(d[0]), "+f"(d[1]), "+f"(d[2]), "+f"(d[3])
        : "r"(a[0]), "r"(a[1]), "r"(a[2]), "r"(a[3]), "r"(b[0]), "r"(b[1]));
}
__device__ __forceinline__ void atomicMaxFloat(float* addr, float v) {
    if (v >= 0.f) atomicMax((int*)addr, __float_as_int(v));
    else          atomicMin((unsigned int*)addr, __float_as_uint(v));
}

// ---------------- kernel 1: fused avg+max 3x3 pooling ----------------------
__global__ void __launch_bounds__(256) pool_kernel(const float* __restrict__ x) {
    __shared__ float tile[9216];
    const float4* s4 = reinterpret_cast<const float4*>(x + (size_t)blockIdx.x * 9216);
    float4* t4 = reinterpret_cast<float4*>(tile);
    #pragma unroll
    for (int i = 0; i < 9; i++)
        t4[threadIdx.x + i*256] = s4[threadIdx.x + i*256];
    __syncthreads();
    size_t base = (size_t)blockIdx.x * 1024;
    #pragma unroll
    for (int it = 0; it < 4; it++) {
        int sp = threadIdx.x + it*256;
        int r1 = sp >> 5, r2 = sp & 31;
        const float* p = &tile[r1*3*96 + r2*3];
        float s = 0.f, m = NEG_INF;
        #pragma unroll
        for (int i = 0; i < 3; i++)
            #pragma unroll
            for (int j = 0; j < 3; j++) {
                float v = p[i*96 + j];
                s += v;
                m = fmaxf(m, v);
            }
        g_qpool[base + sp] = s * (1.f/9.f);
        g_kpool[base + sp] = m;
    }
}

// ---------------- init: zero kmean, -inf rowmax ------------------------------
__global__ void init_kernel() {
    int i = blockIdx.x * 256 + threadIdx.x;
    g_rowmax[i] = NEG_INF;
    if (i < B_*HN_*D_) g_kmean[i] = 0.f;
}

// ---------------- tf32 tensor-core GEMM, 128x128 tile, K-chunk 16 -----------
// MODE 0: C = acc + bias
// MODE 1: C = acc + bias, atomicAdd row sums into raux1[z*M + m]
// MODE 2: C = acc * raux2[z*M + m] (row scale), atomicMax rowmax into raux1
// MODE 3: B elements transformed exp(b - raux2[z*N + n]) on load; per-column
//         sumexp accumulated; epilogue C = resid + acc * inv_sumexp * (1+*wptr)
#define LDP 136
template<bool A_KM, bool B_NK, int MODE>
__global__ void __launch_bounds__(256) mm_tf32(
    const float* __restrict__ A, const float* __restrict__ Bm,
    const float* __restrict__ bias, float* __restrict__ Cc,
    int M, int N, int K,
    int aMod, long long aStride, long long bStride, long long cStride,
    int biasMod, int biasStride,
    float* __restrict__ raux1, const float* __restrict__ raux2,
    const float* __restrict__ resid, const int* __restrict__ wptr)
{
    __shared__ uint32_t As[2][16][LDP];
    __shared__ uint32_t Bs[2][16][LDP];
    __shared__ float ssum[128];

    const int z = blockIdx.z;
    A  += (size_t)(z % aMod) * aStride;
    Bm += (size_t)z * bStride;
    Cc += (size_t)z * cStride;
    if (MODE == 3) resid += (size_t)z * cStride;

    const int bm = blockIdx.y * 128;
    const int bn = blockIdx.x * 128;
    const int tid  = threadIdx.x;
    const int lane = tid & 31;
    const int warp = tid >> 5;
    const int wm = warp >> 1;
    const int wn = warp & 1;
    const int qr = lane >> 2;
    const int cq = lane & 3;

    float acc[2][8][4];
    #pragma unroll
    for (int i = 0; i < 2; i++)
        #pragma unroll
        for (int j = 0; j < 8; j++)
            #pragma unroll
            for (int k = 0; k < 4; k++) acc[i][j][k] = 0.f;

    float pa[8], pb[8];
    float rm0 = 0.f, rm1 = 0.f, se0 = 0.f, se1 = 0.f;
    if (MODE == 3) {
        int nB = tid >> 2;
        rm0 = raux2[(size_t)z * N + bn + nB];
        rm1 = raux2[(size_t)z * N + bn + nB + 64];
    }

    auto loadA = [&](int k0) {
        if (A_KM) {
            int kk = tid >> 5, m4 = (tid & 31) << 2;
            *(float4*)&pa[0] = *(const float4*)&A[(size_t)(k0+kk)  *M + bm + m4];
            *(float4*)&pa[4] = *(const float4*)&A[(size_t)(k0+kk+8)*M + bm + m4];
        } else {
            int m = tid >> 2, kq4 = (tid & 3) << 2;
            *(float4*)&pa[0] = *(const float4*)&A[(size_t)(bm+m)   *K + k0 + kq4];
            *(float4*)&pa[4] = *(const float4*)&A[(size_t)(bm+m+64)*K + k0 + kq4];
        }
    };
    auto loadB = [&](int k0) {
        if (B_NK) {
            int n = tid >> 2, kq4 = (tid & 3) << 2;
            *(float4*)&pb[0] = *(const float4*)&Bm[(size_t)(bn+n)   *K + k0 + kq4];
            *(float4*)&pb[4] = *(const float4*)&Bm[(size_t)(bn+n+64)*K + k0 + kq4];
        } else {
            int kk = tid >> 5, n4 = (tid & 31) << 2;
            *(float4*)&pb[0] = *(const float4*)&Bm[(size_t)(k0+kk)  *N + bn + n4];
            *(float4*)&pb[4] = *(const float4*)&Bm[(size_t)(k0+kk+8)*N + bn + n4];
        }
    };
    auto storeA = [&](int buf) {
        if (A_KM) {
            int kk = tid >> 5, m4 = (tid & 31) << 2;
            uint32_t* p0 = &As[buf][kk][m4];
            uint32_t* p1 = &As[buf][kk+8][m4];
            #pragma unroll
            for (int j = 0; j < 4; j++) { p0[j] = f2tf32(pa[j]); p1[j] = f2tf32(pa[4+j]); }
        } else {
            int m = tid >> 2, kq4 = (tid & 3) << 2;
            #pragma unroll
            for (int j = 0; j < 4; j++) {
                As[buf][kq4+j][m]    = f2tf32(pa[j]);
                As[buf][kq4+j][m+64] = f2tf32(pa[4+j]);
            }
        }
    };
    auto storeB = [&](int buf) {
        if (B_NK) {
            int n = tid >> 2, kq4 = (tid & 3) << 2;
            if (MODE == 3) {
                #pragma unroll
                for (int j = 0; j < 4; j++) {
                    float e0 = __expf(pb[j]   - rm0);
                    float e1 = __expf(pb[4+j] - rm1);
                    se0 += e0; se1 += e1;
                    Bs[buf][kq4+j][n]    = f2tf32(e0);
                    Bs[buf][kq4+j][n+64] = f2tf32(e1);
                }
            } else {
                #pragma unroll
                for (int j = 0; j < 4; j++) {
                    Bs[buf][kq4+j][n]    = f2tf32(pb[j]);
                    Bs[buf][kq4+j][n+64] = f2tf32(pb[4+j]);
                }
            }
        } else {
            int kk = tid >> 5, n4 = (tid & 31) << 2;
            uint32_t* p0 = &Bs[buf][kk][n4];
            uint32_t* p1 = &Bs[buf][kk+8][n4];
            #pragma unroll
            for (int j = 0; j < 4; j++) { p0[j] = f2tf32(pb[j]); p1[j] = f2tf32(pb[4+j]); }
        }
    };
    auto compute = [&](int buf) {
        #pragma unroll
        for (int kk = 0; kk < 16; kk += 8) {
            uint32_t af[2][4], bf[8][2];
            #pragma unroll
            for (int mt = 0; mt < 2; mt++) {
                int mb = wm*32 + mt*16 + qr;
                af[mt][0] = As[buf][kk+cq  ][mb];
                af[mt][1] = As[buf][kk+cq  ][mb+8];
                af[mt][2] = As[buf][kk+cq+4][mb];
                af[mt][3] = As[buf][kk+cq+4][mb+8];
            }
            #pragma unroll
            for (int nt = 0; nt < 8; nt++) {
                int nb = wn*64 + nt*8 + qr;
                bf[nt][0] = Bs[buf][kk+cq  ][nb];
                bf[nt][1] = Bs[buf][kk+cq+4][nb];
            }
            #pragma unroll
            for (int mt = 0; mt < 2; mt++)
                #pragma unroll
                for (int nt = 0; nt < 8; nt++)
                    mma_tf32(acc[mt][nt], af[mt], bf[nt]);
        }
    };

    // ---- pipelined main loop ----
    const int nT = K >> 4;
    loadA(0); loadB(0);
    storeA(0); storeB(0);
    __syncthreads();
    for (int t = 0; t < nT; t++) {
        int buf = t & 1;
        if (t + 1 < nT) { loadA((t+1) << 4); loadB((t+1) << 4); }
        compute(buf);
        if (t + 1 < nT) { storeA(buf ^ 1); storeB(buf ^ 1); }
        __syncthreads();
    }

    // ---- column sumexp reduction (MODE 3) ----
    if (MODE == 3) {
        se0 += __shfl_xor_sync(0xffffffffu, se0, 1);
        se0 += __shfl_xor_sync(0xffffffffu, se0, 2);
        se1 += __shfl_xor_sync(0xffffffffu, se1, 1);
        se1 += __shfl_xor_sync(0xffffffffu, se1, 2);
        if ((tid & 3) == 0) {
            int nB = tid >> 2;
            ssum[nB]      = se0;
            ssum[nB + 64] = se1;
        }
        __syncthreads();
    }

    // ---- epilogue ----
    const float ws = (MODE == 3) ? (1.f + (float)wptr[0]) : 0.f;
    #pragma unroll
    for (int mt = 0; mt < 2; mt++) {
        int row0 = bm + wm*32 + mt*16 + qr;
        float b0 = 0.f, b1 = 0.f;
        if (MODE <= 1) {
            const float* bptr = bias + (size_t)(z % biasMod) * biasStride;
            b0 = bptr[row0]; b1 = bptr[row0 + 8];
        }
        float sc0 = 1.f, sc1 = 1.f;
        if (MODE == 2) {
            sc0 = raux2[(size_t)z * M + row0];
            sc1 = raux2[(size_t)z * M + row0 + 8];
        }
        float s0 = 0.f, s1 = 0.f;             // rowsum (MODE 1)
        float m0 = NEG_INF, m1 = NEG_INF;     // rowmax (MODE 2)
        #pragma unroll
        for (int nt = 0; nt < 8; nt++) {
            int col = bn + wn*64 + nt*8 + cq*2;
            float* d = acc[mt][nt];
            if (MODE == 3) {
                int lc = wn*64 + nt*8 + cq*2;
                float i0 = 1.f / ssum[lc], i1 = 1.f / ssum[lc+1];
                float2 rv0 = *(const float2*)&resid[(size_t)row0    *N + col];
                float2 rv1 = *(const float2*)&resid[(size_t)(row0+8)*N + col];
                *(float2*)&Cc[(size_t)row0    *N + col] =
                    make_float2(rv0.x + d[0]*i0*ws, rv0.y + d[1]*i1*ws);
                *(float2*)&Cc[(size_t)(row0+8)*N + col] =
                    make_float2(rv1.x + d[2]*i0*ws, rv1.y + d[3]*i1*ws);
            } else if (MODE == 2) {
                float v0 = d[0]*sc0, v1 = d[1]*sc0, v2 = d[2]*sc1, v3 = d[3]*sc1;
                *(float2*)&Cc[(size_t)row0    *N + col] = make_float2(v0, v1);
                *(float2*)&Cc[(size_t)(row0+8)*N + col] = make_float2(v2, v3);
                m0 = fmaxf(m0, fmaxf(v0, v1));
                m1 = fmaxf(m1, fmaxf(v2, v3));
            } else {
                *(float2*)&Cc[(size_t)row0    *N + col] = make_float2(d[0] + b0, d[1] + b0);
                *(float2*)&Cc[(size_t)(row0+8)*N + col] = make_float2(d[2] + b1, d[3] + b1);
                if (MODE == 1) { s0 += d[0] + d[1] + 2.f*b0; s1 += d[2] + d[3] + 2.f*b1; }
            }
        }
        if (MODE == 1) {
            s0 += __shfl_xor_sync(0xffffffffu, s0, 1);
            s0 += __shfl_xor_sync(0xffffffffu, s0, 2);
            s1 += __shfl_xor_sync(0xffffffffu, s1, 1);
            s1 += __shfl_xor_sync(0xffffffffu, s1, 2);
            if (cq == 0) {
                atomicAdd(&raux1[(size_t)z * M + row0],     s0);
                atomicAdd(&raux1[(size_t)z * M + row0 + 8], s1);
            }
        }
        if (MODE == 2) {
            m0 = fmaxf(m0, __shfl_xor_sync(0xffffffffu, m0, 1));
            m0 = fmaxf(m0, __shfl_xor_sync(0xffffffffu, m0, 2));
            m1 = fmaxf(m1, __shfl_xor_sync(0xffffffffu, m1, 1));
            m1 = fmaxf(m1, __shfl_xor_sync(0xffffffffu, m1, 2));
            if (cq == 0) {
                atomicMaxFloat(&raux1[(size_t)z * M + row0],     m0);
                atomicMaxFloat(&raux1[(size_t)z * M + row0 + 8], m1);
            }
        }
    }
}

// ---------------- kernel: kmean x Qt -> p gate -> row scale ------------------
// rowmean[c] = mean_e' S[c,e'] = sum_e Qt[e,c] * kmean[e]   (exact identity)
__global__ void __launch_bounds__(512) pgate_kernel(const float* __restrict__ Wp,
                                                    const float* __restrict__ bp) {
    const int z = blockIdx.x;
    __shared__ float km[128];
    __shared__ float msh[512];
    const int tid = threadIdx.x;
    if (tid < 128) km[tid] = g_kmean[(size_t)z * 128 + tid] * (1.f/512.f);
    __syncthreads();

    const float* Qz = g_Qt + (size_t)z * 65536;
    float rm = 0.f;
    #pragma unroll 4
    for (int e = 0; e < 128; e++) rm = fmaf(Qz[(size_t)e * 512 + tid], km[e], rm);
    msh[tid] = rm;
    __syncthreads();

    float accv = bp[tid];
    const float* wrow = Wp + (size_t)tid * 512;
    #pragma unroll 4
    for (int j = 0; j < 512; j++) accv = fmaf(msh[j], wrow[j], accv);
    float p = 1.f / (1.f + expf(-accv));
    g_rowscale[(size_t)z * 512 + tid] = exp2f(-7.f * (0.5f + p));   // D^{-(0.5+p)}
}

// ---------------- launch ----------------------------------------------------
extern "C" void kernel_launch(void* const* d_in, const int* in_sizes, int n_in,
                              void* d_out, int out_size) {
    const float* x   = (const float*)d_in[0];
    const float* Wqk = (const float*)d_in[1];
    const float* bqk = (const float*)d_in[2];
    const float* Wp  = (const float*)d_in[3];
    const float* bp  = (const float*)d_in[4];
    const float* Wv  = (const float*)d_in[5];
    const float* bv  = (const float*)d_in[6];
    const int*   wgt = (const int*)d_in[7];
    float* out = (float*)d_out;

    float *qpool, *kpool, *vpool, *Qt, *Kt, *S, *kmean, *rowmax, *rowscale;
    cudaGetSymbolAddress((void**)&qpool,    g_qpool);
    cudaGetSymbolAddress((void**)&kpool,    g_kpool);
    cudaGetSymbolAddress((void**)&vpool,    g_vpool);
    cudaGetSymbolAddress((void**)&Qt,       g_Qt);
    cudaGetSymbolAddress((void**)&Kt,       g_Kt);
    cudaGetSymbolAddress((void**)&S,        g_S);
    cudaGetSymbolAddress((void**)&kmean,    g_kmean);
    cudaGetSymbolAddress((void**)&rowmax,   g_rowmax);
    cudaGetSymbolAddress((void**)&rowscale, g_rowscale);

    // 1) fused avg/max pooling; init kmean/rowmax
    pool_kernel<<<8192, 256>>>(x);
    init_kernel<<<256, 256>>>();

    // 2) vpool[b] = Wv @ qpool[b] + bv
    mm_tf32<false,false,0><<<dim3(8,4,16), 256>>>(
        Wv, qpool, bv, vpool, 512, 1024, 512,
        1, 0, 524288, 524288, 1, 0, nullptr, nullptr, nullptr, nullptr);

    // 3) Kt[z] = Wqk[h] @ kpool_block[z] + bqk[h]  (+ fused row sums -> kmean)
    mm_tf32<false,false,1><<<dim3(4,1,128), 256>>>(
        Wqk, kpool, bqk, Kt, 128, 512, 128,
        8, 16384, 65536, 65536, 8, 128, kmean, nullptr, nullptr, nullptr);

    // 4) Qt[z] = Wqk[h] @ qpool_block[z] + bqk[h]
    mm_tf32<false,false,0><<<dim3(4,1,128), 256>>>(
        Wqk, qpool, bqk, Qt, 128, 512, 128,
        8, 16384, 65536, 65536, 8, 128, nullptr, nullptr, nullptr, nullptr);

    // 5) gate: rowmean = Qt . kmean -> sigmoid -> rowscale (before scores!)
    pgate_kernel<<<128, 512>>>(Wp, bp);

    // 6) S[z] = (Qt[z]^T @ Kt[z]) * rowscale   (+ fused rowmax atomics)
    mm_tf32<true,false,2><<<dim3(4,4,128), 256>>>(
        Qt, Kt, nullptr, S, 512, 512, 128,
        1<<30, 65536, 65536, 262144, 1, 0, rowmax, rowscale, nullptr, nullptr);

    // 7) out[z] = qpool[z] + (V @ softmax(S)^T) * (1+weight)
    //    exp + normalize fused into the GEMM B-operand path
    mm_tf32<false,true,3><<<dim3(4,1,128), 256>>>(
        vpool, S, nullptr, out, 128, 512, 512,
        1<<30, 65536, 262144, 65536, 1, 0, nullptr, rowmax, qpool, wgt);
}

// round 7
// speedup vs baseline: 2.5068x; 1.1693x over previous
#include <cuda_runtime.h>
#include <math.h>
#include <stdint.h>

// Problem constants
#define B_   16
#define C_   512
#define SP_  1024          // R*R
#define HN_  8
#define D_   128
#define NEG_INF -3.4e38f
// x is [16, 512, 96, 96]

// ---------------- scratch (static device arrays; no allocation) -------------
__device__ float g_qpool[B_*C_*SP_];        // flat [b][c*1024+sp]
__device__ float g_kpool[B_*C_*SP_];
__device__ float g_vpool[B_*C_*SP_];
__device__ float g_Qt[B_*HN_*D_*C_];        // [z=b*8+h][e*512 + c]
__device__ float g_Kt[B_*HN_*D_*C_];
__device__ float g_S [B_*HN_*C_*C_];        // exp(scaled scores) [z][c*512 + e]
__device__ float g_kmean[B_*HN_*D_];        // row sums of Kt (over c)
__device__ float g_sumexp[B_*HN_*C_];       // per-(z,c) sum of exp(scaled scores)
__device__ float g_rowscale[B_*HN_*C_];

// ---------------- helpers ----------------------------------------------------
__device__ __forceinline__ void mma_tf32(float* d, const uint32_t* a, const uint32_t* b) {
    asm volatile("mma.sync.aligned.m16n8k8.row.col.f32.tf32.tf32.f32 "
        "{%0,%1,%2,%3}, {%4,%5,%6,%7}, {%8,%9}, {%0,%1,%2,%3};"
        : "+f"(d[0]), "+f"(d[1]), "+f"(d[2]), "+f"(d[3])
        : "r"(a[0]), "r"(a[1]), "r"(a[2]), "r"(a[3]), "r"(b[0]), "r"(b[1]));
}
__device__ __forceinline__ void cpa16(uint32_t* dst, const float* src) {
    uint32_t d = (uint32_t)__cvta_generic_to_shared(dst);
    asm volatile("cp.async.cg.shared.global [%0], [%1], 16;" :: "r"(d), "l"(src));
}

// ---------------- kernel 1: fused avg+max 3x3 pooling ----------------------
__global__ void __launch_bounds__(256) pool_kernel(const float* __restrict__ x) {
    __shared__ float tile[9216];
    const float4* s4 = reinterpret_cast<const float4*>(x + (size_t)blockIdx.x * 9216);
    float4* t4 = reinterpret_cast<float4*>(tile);
    #pragma unroll
    for (int i = 0; i < 9; i++)
        t4[threadIdx.x + i*256] = s4[threadIdx.x + i*256];
    __syncthreads();
    size_t base = (size_t)blockIdx.x * 1024;
    #pragma unroll
    for (int it = 0; it < 4; it++) {
        int sp = threadIdx.x + it*256;
        int r1 = sp >> 5, r2 = sp & 31;
        const float* p = &tile[r1*3*96 + r2*3];
        float s = 0.f, m = NEG_INF;
        #pragma unroll
        for (int i = 0; i < 3; i++)
            #pragma unroll
            for (int j = 0; j < 3; j++) {
                float v = p[i*96 + j];
                s += v;
                m = fmaxf(m, v);
            }
        g_qpool[base + sp] = s * (1.f/9.f);
        g_kpool[base + sp] = m;
    }
}

// ---------------- init: zero sumexp + kmean ----------------------------------
__global__ void init_kernel() {
    int i = blockIdx.x * 256 + threadIdx.x;
    g_sumexp[i] = 0.f;
    if (i < B_*HN_*D_) g_kmean[i] = 0.f;
}

// ---------------- tf32 tensor-core GEMM, 128x128 tile, cp.async 4-stage ------
// MODE 0: C = acc + bias
// MODE 1: C = acc + bias, atomicAdd row sums into raux1[z*M + m]
// MODE 2: C = exp(acc * raux2[z*M+m]), atomicAdd row sums into raux1[z*M+m]
// MODE 3: C = resid + acc * (1/raux2[z*N+n]) * (1 + *wptr)
// smem layouts (uint32 words):
//   "MK" rows of 16 k + pad4   -> stride 20  (outer-major operands)
//   "KM" rows of 128 x + pad8  -> stride 136 (k-major operands)
template<bool A_KM, bool B_NK, int MODE>
__global__ void __launch_bounds__(256) mm_tf32(
    const float* __restrict__ A, const float* __restrict__ Bm,
    const float* __restrict__ bias, float* __restrict__ Cc,
    int M, int N, int K,
    int aMod, long long aStride, long long bStride, long long cStride,
    int biasMod, int biasStride,
    float* __restrict__ raux1, const float* __restrict__ raux2,
    const float* __restrict__ resid, const int* __restrict__ wptr)
{
    constexpr int STAGES = 4;
    constexpr int AW = A_KM ? 16*136 : 128*20;
    constexpr int BW = B_NK ? 128*20 : 16*136;
    extern __shared__ uint32_t dsm[];
    uint32_t* As = dsm;
    uint32_t* Bs = dsm + STAGES*AW;
    __shared__ float sS[128];

    const int z = blockIdx.z;
    A  += (size_t)(z % aMod) * aStride;
    Bm += (size_t)z * bStride;
    Cc += (size_t)z * cStride;
    if (MODE == 3) resid += (size_t)z * cStride;

    const int bm = blockIdx.y * 128;
    const int bn = blockIdx.x * 128;
    const int tid  = threadIdx.x;
    const int lane = tid & 31;
    const int warp = tid >> 5;
    const int wm = warp >> 1;
    const int wn = warp & 1;
    const int qr = lane >> 2;
    const int cq = lane & 3;

    float acc[2][8][4];
    #pragma unroll
    for (int i = 0; i < 2; i++)
        #pragma unroll
        for (int j = 0; j < 8; j++)
            #pragma unroll
            for (int k = 0; k < 4; k++) acc[i][j][k] = 0.f;

    auto issue = [&](int t) {
        int buf = t & (STAGES-1);
        int k0 = t << 4;
        uint32_t* Ab = As + buf*AW;
        uint32_t* Bb = Bs + buf*BW;
        if (A_KM) {
            int k = tid >> 5, m4 = (tid & 31) << 2;
            cpa16(Ab + k*136 + m4,       A + (size_t)(k0+k)  *M + bm + m4);
            cpa16(Ab + (k+8)*136 + m4,   A + (size_t)(k0+k+8)*M + bm + m4);
        } else {
            int m = tid >> 2, kq = (tid & 3) << 2;
            cpa16(Ab + m*20 + kq,        A + (size_t)(bm+m)   *K + k0 + kq);
            cpa16(Ab + (m+64)*20 + kq,   A + (size_t)(bm+m+64)*K + k0 + kq);
        }
        if (B_NK) {
            int n = tid >> 2, kq = (tid & 3) << 2;
            cpa16(Bb + n*20 + kq,        Bm + (size_t)(bn+n)   *K + k0 + kq);
            cpa16(Bb + (n+64)*20 + kq,   Bm + (size_t)(bn+n+64)*K + k0 + kq);
        } else {
            int k = tid >> 5, n4 = (tid & 31) << 2;
            cpa16(Bb + k*136 + n4,       Bm + (size_t)(k0+k)  *N + bn + n4);
            cpa16(Bb + (k+8)*136 + n4,   Bm + (size_t)(k0+k+8)*N + bn + n4);
        }
        asm volatile("cp.async.commit_group;" ::: "memory");
    };

    auto compute = [&](int buf) {
        const uint32_t* Ab = As + buf*AW;
        const uint32_t* Bb = Bs + buf*BW;
        #pragma unroll
        for (int kk = 0; kk < 16; kk += 8) {
            uint32_t af[2][4], bf[8][2];
            #pragma unroll
            for (int mt = 0; mt < 2; mt++) {
                int mb = wm*32 + mt*16 + qr;
                if (A_KM) {
                    af[mt][0] = Ab[(kk+cq)  *136 + mb];
                    af[mt][1] = Ab[(kk+cq)  *136 + mb+8];
                    af[mt][2] = Ab[(kk+cq+4)*136 + mb];
                    af[mt][3] = Ab[(kk+cq+4)*136 + mb+8];
                } else {
                    af[mt][0] = Ab[mb    *20 + kk+cq];
                    af[mt][1] = Ab[(mb+8)*20 + kk+cq];
                    af[mt][2] = Ab[mb    *20 + kk+cq+4];
                    af[mt][3] = Ab[(mb+8)*20 + kk+cq+4];
                }
            }
            #pragma unroll
            for (int nt = 0; nt < 8; nt++) {
                int nb = wn*64 + nt*8 + qr;
                if (B_NK) {
                    bf[nt][0] = Bb[nb*20 + kk+cq];
                    bf[nt][1] = Bb[nb*20 + kk+cq+4];
                } else {
                    bf[nt][0] = Bb[(kk+cq)  *136 + nb];
                    bf[nt][1] = Bb[(kk+cq+4)*136 + nb];
                }
            }
            #pragma unroll
            for (int mt = 0; mt < 2; mt++)
                #pragma unroll
                for (int nt = 0; nt < 8; nt++)
                    mma_tf32(acc[mt][nt], af[mt], bf[nt]);
        }
    };

    // ---- pipelined main loop ----
    const int nT = K >> 4;
    #pragma unroll
    for (int s = 0; s < STAGES-1; s++) issue(s);
    if (MODE == 3 && tid < 128)
        sS[tid] = 1.f / raux2[(size_t)z * N + bn + tid];
    for (int t = 0; t < nT; t++) {
        asm volatile("cp.async.wait_group 2;" ::: "memory");
        __syncthreads();
        if (t + STAGES-1 < nT) issue(t + STAGES-1);
        else asm volatile("cp.async.commit_group;" ::: "memory");
        compute(t & (STAGES-1));
    }

    // ---- epilogue ----
    const float ws = (MODE == 3) ? (1.f + (float)wptr[0]) : 0.f;
    #pragma unroll
    for (int mt = 0; mt < 2; mt++) {
        int row0 = bm + wm*32 + mt*16 + qr;
        float b0 = 0.f, b1 = 0.f;
        if (MODE <= 1) {
            const float* bptr = bias + (size_t)(z % biasMod) * biasStride;
            b0 = bptr[row0]; b1 = bptr[row0 + 8];
        }
        float sc0 = 0.f, sc1 = 0.f;
        if (MODE == 2) {
            sc0 = raux2[(size_t)z * M + row0];
            sc1 = raux2[(size_t)z * M + row0 + 8];
        }
        float s0 = 0.f, s1 = 0.f;             // row sums (MODE 1/2)
        #pragma unroll
        for (int nt = 0; nt < 8; nt++) {
            int col = bn + wn*64 + nt*8 + cq*2;
            float* d = acc[mt][nt];
            if (MODE == 3) {
                int lc = wn*64 + nt*8 + cq*2;
                float i0 = sS[lc], i1 = sS[lc+1];
                float2 rv0 = *(const float2*)&resid[(size_t)row0    *N + col];
                float2 rv1 = *(const float2*)&resid[(size_t)(row0+8)*N + col];
                *(float2*)&Cc[(size_t)row0    *N + col] =
                    make_float2(rv0.x + d[0]*i0*ws, rv0.y + d[1]*i1*ws);
                *(float2*)&Cc[(size_t)(row0+8)*N + col] =
                    make_float2(rv1.x + d[2]*i0*ws, rv1.y + d[3]*i1*ws);
            } else if (MODE == 2) {
                float v0 = __expf(d[0]*sc0), v1 = __expf(d[1]*sc0);
                float v2 = __expf(d[2]*sc1), v3 = __expf(d[3]*sc1);
                *(float2*)&Cc[(size_t)row0    *N + col] = make_float2(v0, v1);
                *(float2*)&Cc[(size_t)(row0+8)*N + col] = make_float2(v2, v3);
                s0 += v0 + v1; s1 += v2 + v3;
            } else {
                *(float2*)&Cc[(size_t)row0    *N + col] = make_float2(d[0] + b0, d[1] + b0);
                *(float2*)&Cc[(size_t)(row0+8)*N + col] = make_float2(d[2] + b1, d[3] + b1);
                if (MODE == 1) { s0 += d[0] + d[1] + 2.f*b0; s1 += d[2] + d[3] + 2.f*b1; }
            }
        }
        if (MODE == 1 || MODE == 2) {
            s0 += __shfl_xor_sync(0xffffffffu, s0, 1);
            s0 += __shfl_xor_sync(0xffffffffu, s0, 2);
            s1 += __shfl_xor_sync(0xffffffffu, s1, 1);
            s1 += __shfl_xor_sync(0xffffffffu, s1, 2);
            if (cq == 0) {
                atomicAdd(&raux1[(size_t)z * M + row0],     s0);
                atomicAdd(&raux1[(size_t)z * M + row0 + 8], s1);
            }
        }
    }
}

// ---------------- kernel: kmean x Qt -> p gate -> row scale ------------------
// rowmean[c] = mean_e' S[c,e'] = sum_e Qt[e,c] * kmean[e]   (exact identity)
__global__ void __launch_bounds__(512) pgate_kernel(const float* __restrict__ Wp,
                                                    const float* __restrict__ bp) {
    const int z = blockIdx.x;
    __shared__ float km[128];
    __shared__ float msh[512];
    const int tid = threadIdx.x;
    if (tid < 128) km[tid] = g_kmean[(size_t)z * 128 + tid] * (1.f/512.f);
    __syncthreads();

    const float* Qz = g_Qt + (size_t)z * 65536;
    float rm = 0.f;
    #pragma unroll 4
    for (int e = 0; e < 128; e++) rm = fmaf(Qz[(size_t)e * 512 + tid], km[e], rm);
    msh[tid] = rm;
    __syncthreads();

    float accv = bp[tid];
    const float* wrow = Wp + (size_t)tid * 512;
    #pragma unroll 4
    for (int j = 0; j < 512; j++) accv = fmaf(msh[j], wrow[j], accv);
    float p = 1.f / (1.f + expf(-accv));
    g_rowscale[(size_t)z * 512 + tid] = exp2f(-7.f * (0.5f + p));   // D^{-(0.5+p)}
}

// ---------------- launch ----------------------------------------------------
extern "C" void kernel_launch(void* const* d_in, const int* in_sizes, int n_in,
                              void* d_out, int out_size) {
    const float* x   = (const float*)d_in[0];
    const float* Wqk = (const float*)d_in[1];
    const float* bqk = (const float*)d_in[2];
    const float* Wp  = (const float*)d_in[3];
    const float* bp  = (const float*)d_in[4];
    const float* Wv  = (const float*)d_in[5];
    const float* bv  = (const float*)d_in[6];
    const int*   wgt = (const int*)d_in[7];
    float* out = (float*)d_out;

    float *qpool, *kpool, *vpool, *Qt, *Kt, *S, *kmean, *sumexp, *rowscale;
    cudaGetSymbolAddress((void**)&qpool,    g_qpool);
    cudaGetSymbolAddress((void**)&kpool,    g_kpool);
    cudaGetSymbolAddress((void**)&vpool,    g_vpool);
    cudaGetSymbolAddress((void**)&Qt,       g_Qt);
    cudaGetSymbolAddress((void**)&Kt,       g_Kt);
    cudaGetSymbolAddress((void**)&S,        g_S);
    cudaGetSymbolAddress((void**)&kmean,    g_kmean);
    cudaGetSymbolAddress((void**)&sumexp,   g_sumexp);
    cudaGetSymbolAddress((void**)&rowscale, g_rowscale);

    // dynamic smem opt-in (idempotent)
    static bool attr_done = false;
    if (!attr_done) {
        cudaFuncSetAttribute(mm_tf32<false,false,0>, cudaFuncAttributeMaxDynamicSharedMemorySize, 75776);
        cudaFuncSetAttribute(mm_tf32<false,false,1>, cudaFuncAttributeMaxDynamicSharedMemorySize, 75776);
        cudaFuncSetAttribute(mm_tf32<true, false,2>, cudaFuncAttributeMaxDynamicSharedMemorySize, 69632);
        cudaFuncSetAttribute(mm_tf32<false,true, 3>, cudaFuncAttributeMaxDynamicSharedMemorySize, 81920);
        attr_done = true;
    }

    // 1) fused avg/max pooling; init sumexp/kmean
    pool_kernel<<<8192, 256>>>(x);
    init_kernel<<<256, 256>>>();

    // 2) vpool[b] = Wv @ qpool[b] + bv
    mm_tf32<false,false,0><<<dim3(8,4,16), 256, 75776>>>(
        Wv, qpool, bv, vpool, 512, 1024, 512,
        1, 0, 524288, 524288, 1, 0, nullptr, nullptr, nullptr, nullptr);

    // 3) Kt[z] = Wqk[h] @ kpool_block[z] + bqk[h]  (+ fused row sums -> kmean)
    mm_tf32<false,false,1><<<dim3(4,1,128), 256, 75776>>>(
        Wqk, kpool, bqk, Kt, 128, 512, 128,
        8, 16384, 65536, 65536, 8, 128, kmean, nullptr, nullptr, nullptr);

    // 4) Qt[z] = Wqk[h] @ qpool_block[z] + bqk[h]
    mm_tf32<false,false,0><<<dim3(4,1,128), 256, 75776>>>(
        Wqk, qpool, bqk, Qt, 128, 512, 128,
        8, 16384, 65536, 65536, 8, 128, nullptr, nullptr, nullptr, nullptr);

    // 5) gate: rowmean = Qt . kmean -> sigmoid -> rowscale (before scores!)
    pgate_kernel<<<128, 512>>>(Wp, bp);

    // 6) S[z] = exp((Qt[z]^T @ Kt[z]) * rowscale)  (+ fused sumexp atomics)
    //    (scores are provably small; softmax shift-invariance makes no-max exact)
    mm_tf32<true,false,2><<<dim3(4,4,128), 256, 69632>>>(
        Qt, Kt, nullptr, S, 512, 512, 128,
        1<<30, 65536, 65536, 262144, 1, 0, sumexp, rowscale, nullptr, nullptr);

    // 7) out[z] = qpool[z] + (V @ expS^T) * (1/sumexp) * (1+weight)
    mm_tf32<false,true,3><<<dim3(4,1,128), 256, 81920>>>(
        vpool, S, nullptr, out, 128, 512, 512,
        1<<30, 65536, 262144, 65536, 1, 0, nullptr, sumexp, qpool, wgt);
}

// round 9
// speedup vs baseline: 3.0939x; 1.2342x over previous
#include <cuda_runtime.h>
#include <cuda_fp16.h>
#include <math.h>
#include <stdint.h>

// Problem constants
#define B_   16
#define C_   512
#define SP_  1024          // R*R
#define HN_  8
#define D_   128
#define NEG_INF -3.4e38f
// x is [16, 512, 96, 96]

// ---------------- scratch (static device arrays; no allocation) -------------
__device__ float  g_qpool [B_*C_*SP_];      // fp32, residual + attn resid input
__device__ __half g_qpoolh[B_*C_*SP_];      // fp16 GEMM operand
__device__ __half g_kpoolh[B_*C_*SP_];
__device__ __half g_vpoolh[B_*C_*SP_];
__device__ __half g_Qth[B_*HN_*D_*C_];      // [z][e*512 + c]
__device__ __half g_Kth[B_*HN_*D_*C_];
__device__ __half g_Sh [B_*HN_*C_*C_];      // exp(scaled scores)*2^-4, [z][c*512+e]
__device__ __half g_Wvh [C_*C_];
__device__ __half g_Wqkh[HN_*D_*D_];
__device__ float  g_kmean[B_*HN_*D_];       // row sums of Kt (over c), fp32
__device__ float  g_sumexp[B_*HN_*C_];      // per-(z,c) sum of exp*2^-4, fp32
__device__ float  g_rowscale[B_*HN_*C_];

// ---------------- helpers ----------------------------------------------------
__device__ __forceinline__ void mma_f16(float* d, const uint32_t* a, const uint32_t* b) {
    asm volatile("mma.sync.aligned.m16n8k16.row.col.f32.f16.f16.f32 "
        "{%0,%1,%2,%3}, {%4,%5,%6,%7}, {%8,%9}, {%0,%1,%2,%3};"
        : "+f"(d[0]), "+f"(d[1]), "+f"(d[2]), "+f"(d[3])
        : "r"(a[0]), "r"(a[1]), "r"(a[2]), "r"(a[3]), "r"(b[0]), "r"(b[1]));
}
__device__ __forceinline__ void ldsm4(uint32_t& r0, uint32_t& r1, uint32_t& r2, uint32_t& r3,
                                      uint32_t addr) {
    asm volatile("ldmatrix.sync.aligned.m8n8.x4.shared.b16 {%0,%1,%2,%3}, [%4];"
        : "=r"(r0), "=r"(r1), "=r"(r2), "=r"(r3) : "r"(addr));
}
__device__ __forceinline__ void ldsm4t(uint32_t& r0, uint32_t& r1, uint32_t& r2, uint32_t& r3,
                                       uint32_t addr) {
    asm volatile("ldmatrix.sync.aligned.m8n8.x4.trans.shared.b16 {%0,%1,%2,%3}, [%4];"
        : "=r"(r0), "=r"(r1), "=r"(r2), "=r"(r3) : "r"(addr));
}
__device__ __forceinline__ void cpa16(__half* dst, const __half* src) {
    uint32_t d = (uint32_t)__cvta_generic_to_shared(dst);
    asm volatile("cp.async.cg.shared.global [%0], [%1], 16;" :: "r"(d), "l"(src));
}

// ---------------- kernel 1: fused avg+max 3x3 pooling ----------------------
__global__ void __launch_bounds__(256) pool_kernel(const float* __restrict__ x) {
    __shared__ float tile[9216];
    const float4* s4 = reinterpret_cast<const float4*>(x + (size_t)blockIdx.x * 9216);
    float4* t4 = reinterpret_cast<float4*>(tile);
    #pragma unroll
    for (int i = 0; i < 9; i++)
        t4[threadIdx.x + i*256] = s4[threadIdx.x + i*256];
    __syncthreads();
    size_t base = (size_t)blockIdx.x * 1024;
    #pragma unroll
    for (int it = 0; it < 4; it++) {
        int sp = threadIdx.x + it*256;
        int r1 = sp >> 5, r2 = sp & 31;
        const float* p = &tile[r1*3*96 + r2*3];
        float s = 0.f, m = NEG_INF;
        #pragma unroll
        for (int i = 0; i < 3; i++)
            #pragma unroll
            for (int j = 0; j < 3; j++) {
                float v = p[i*96 + j];
                s += v;
                m = fmaxf(m, v);
            }
        float a = s * (1.f/9.f);
        g_qpool [base + sp] = a;
        g_qpoolh[base + sp] = __float2half_rn(a);
        g_kpoolh[base + sp] = __float2half_rn(m);
    }
}

// ---------------- init + weight conversion -----------------------------------
__global__ void init_kernel() {
    int i = blockIdx.x * 256 + threadIdx.x;
    g_sumexp[i] = 0.f;
    if (i < B_*HN_*D_) g_kmean[i] = 0.f;
}
__global__ void cvt_kernel(const float* __restrict__ src, __half* __restrict__ dst) {
    int i = blockIdx.x * 256 + threadIdx.x;
    dst[i] = __float2half_rn(src[i]);
}

// ---------------- fp16 tensor-core GEMM, 128x128 tile, K-chunk 32, 4 stages --
// MODE 0: C(h) = acc + bias
// MODE 1: C(h) = acc + bias, atomicAdd row sums into raux1[z*M+m]
// MODE 2: C(h) = exp(acc * raux2[z*M+m]) * 2^-4, atomicAdd row sums -> raux1
// MODE 3: C(f32) = resid + acc * (1/raux2[z*N+n]) * (1 + *wptr)
// smem layouts (fp16 units):
//   outer-major: 128 rows x 32 k, stride 40  (MK / NK)
//   k-major:      32 rows x 128,  stride 136 (KM / KN)
template<bool A_KM, bool B_NK, int MODE>
__global__ void __launch_bounds__(256) mm_f16(
    const __half* __restrict__ A, const __half* __restrict__ Bm,
    const float* __restrict__ bias, void* __restrict__ Cc,
    int M, int N, int K,
    int aMod, long long aStride, long long bStride, long long cStride,
    int biasMod, int biasStride,
    float* __restrict__ raux1, const float* __restrict__ raux2,
    const float* __restrict__ resid, const int* __restrict__ wptr)
{
    constexpr int STAGES = 4;
    constexpr int AW = A_KM ? 32*136 : 128*40;   // fp16 units per stage
    constexpr int BW = B_NK ? 128*40 : 32*136;
    extern __shared__ __half dsm[];
    __half* As = dsm;
    __half* Bs = dsm + STAGES*AW;
    __shared__ float sS[128];

    const int z = blockIdx.z;
    A  += (size_t)(z % aMod) * aStride;
    Bm += (size_t)z * bStride;

    const int bm = blockIdx.y * 128;
    const int bn = blockIdx.x * 128;
    const int tid  = threadIdx.x;
    const int lane = tid & 31;
    const int warp = tid >> 5;
    const int wm = warp >> 1;
    const int wn = warp & 1;
    const int qr = lane >> 2;
    const int cq = lane & 3;

    float acc[2][8][4];
    #pragma unroll
    for (int i = 0; i < 2; i++)
        #pragma unroll
        for (int j = 0; j < 8; j++)
            #pragma unroll
            for (int k = 0; k < 4; k++) acc[i][j][k] = 0.f;

    auto issue = [&](int t) {
        int buf = t & (STAGES-1);
        int k0 = t << 5;
        __half* Ab = As + buf*AW;
        __half* Bb = Bs + buf*BW;
        if (A_KM) {
            int k = tid >> 4, c = tid & 15;
            cpa16(Ab + k*136 + c*8,       A + (size_t)(k0+k)   *M + bm + c*8);
            cpa16(Ab + (k+16)*136 + c*8,  A + (size_t)(k0+k+16)*M + bm + c*8);
        } else {
            int m = tid >> 2, c = tid & 3;
            cpa16(Ab + m*40 + c*8,        A + (size_t)(bm+m)   *K + k0 + c*8);
            cpa16(Ab + (m+64)*40 + c*8,   A + (size_t)(bm+m+64)*K + k0 + c*8);
        }
        if (B_NK) {
            int n = tid >> 2, c = tid & 3;
            cpa16(Bb + n*40 + c*8,        Bm + (size_t)(bn+n)   *K + k0 + c*8);
            cpa16(Bb + (n+64)*40 + c*8,   Bm + (size_t)(bn+n+64)*K + k0 + c*8);
        } else {
            int k = tid >> 4, c = tid & 15;
            cpa16(Bb + k*136 + c*8,       Bm + (size_t)(k0+k)   *N + bn + c*8);
            cpa16(Bb + (k+16)*136 + c*8,  Bm + (size_t)(k0+k+16)*N + bn + c*8);
        }
        asm volatile("cp.async.commit_group;" ::: "memory");
    };

    const uint32_t aSm = (uint32_t)__cvta_generic_to_shared(As);
    const uint32_t bSm = (uint32_t)__cvta_generic_to_shared(Bs);

    auto compute = [&](int buf) {
        const uint32_t aBase = aSm + buf*AW*2;
        const uint32_t bBase = bSm + buf*BW*2;
        #pragma unroll
        for (int kk = 0; kk < 32; kk += 16) {
            uint32_t af[2][4], bf[8][2];
            #pragma unroll
            for (int mt = 0; mt < 2; mt++) {
                if (A_KM) {
                    uint32_t ad = aBase +
                        (((kk + (lane&7) + ((lane&16)>>1)) * 136) +
                          wm*32 + mt*16 + (lane&8)) * 2;
                    ldsm4t(af[mt][0], af[mt][1], af[mt][2], af[mt][3], ad);
                } else {
                    uint32_t ad = aBase +
                        (((wm*32 + mt*16 + (lane&15)) * 40) +
                          kk + ((lane&16)>>1)) * 2;
                    ldsm4(af[mt][0], af[mt][1], af[mt][2], af[mt][3], ad);
                }
            }
            #pragma unroll
            for (int j = 0; j < 4; j++) {
                if (B_NK) {
                    uint32_t bd = bBase +
                        (((wn*64 + j*16 + (lane&7) + ((lane&16)>>1)) * 40) +
                          kk + (lane&8)) * 2;
                    ldsm4(bf[2*j][0], bf[2*j][1], bf[2*j+1][0], bf[2*j+1][1], bd);
                } else {
                    uint32_t bd = bBase +
                        (((kk + (lane&7) + (lane&8)) * 136) +
                          wn*64 + j*16 + ((lane&16)>>1)) * 2;
                    ldsm4t(bf[2*j][0], bf[2*j][1], bf[2*j+1][0], bf[2*j+1][1], bd);
                }
            }
            #pragma unroll
            for (int mt = 0; mt < 2; mt++)
                #pragma unroll
                for (int nt = 0; nt < 8; nt++)
                    mma_f16(acc[mt][nt], af[mt], bf[nt]);
        }
    };

    // ---- pipelined main loop ----
    const int nT = K >> 5;
    #pragma unroll
    for (int s = 0; s < STAGES-1; s++) issue(s);
    if (MODE == 3 && tid < 128)
        sS[tid] = 1.f / raux2[(size_t)z * N + bn + tid];
    for (int t = 0; t < nT; t++) {
        asm volatile("cp.async.wait_group 2;" ::: "memory");
        __syncthreads();
        if (t + STAGES-1 < nT) issue(t + STAGES-1);
        else asm volatile("cp.async.commit_group;" ::: "memory");
        compute(t & (STAGES-1));
    }

    // ---- epilogue ----
    __half* Ch = (__half*)Cc + (MODE == 3 ? 0 : (size_t)z * cStride);
    float*  Cf = (float*)Cc + (size_t)z * cStride;
    const float* rz = (MODE == 3) ? resid + (size_t)z * cStride : nullptr;
    const float ws = (MODE == 3) ? (1.f + (float)wptr[0]) : 0.f;
    #pragma unroll
    for (int mt = 0; mt < 2; mt++) {
        int row0 = bm + wm*32 + mt*16 + qr;
        float b0 = 0.f, b1 = 0.f;
        if (MODE <= 1) {
            const float* bptr = bias + (size_t)(z % biasMod) * biasStride;
            b0 = bptr[row0]; b1 = bptr[row0 + 8];
        }
        float sc0 = 0.f, sc1 = 0.f;
        if (MODE == 2) {
            sc0 = raux2[(size_t)z * M + row0];
            sc1 = raux2[(size_t)z * M + row0 + 8];
        }
        float s0 = 0.f, s1 = 0.f;
        #pragma unroll
        for (int nt = 0; nt < 8; nt++) {
            int col = bn + wn*64 + nt*8 + cq*2;
            float* d = acc[mt][nt];
            if (MODE == 3) {
                int lc = wn*64 + nt*8 + cq*2;
                float i0 = sS[lc], i1 = sS[lc+1];
                float2 rv0 = *(const float2*)&rz[(size_t)row0    *N + col];
                float2 rv1 = *(const float2*)&rz[(size_t)(row0+8)*N + col];
                *(float2*)&Cf[(size_t)row0    *N + col] =
                    make_float2(rv0.x + d[0]*i0*ws, rv0.y + d[1]*i1*ws);
                *(float2*)&Cf[(size_t)(row0+8)*N + col] =
                    make_float2(rv1.x + d[2]*i0*ws, rv1.y + d[3]*i1*ws);
            } else if (MODE == 2) {
                float v0 = __expf(d[0]*sc0)*0.0625f, v1 = __expf(d[1]*sc0)*0.0625f;
                float v2 = __expf(d[2]*sc1)*0.0625f, v3 = __expf(d[3]*sc1)*0.0625f;
                *(__half2*)&Ch[(size_t)row0    *N + col] = __floats2half2_rn(v0, v1);
                *(__half2*)&Ch[(size_t)(row0+8)*N + col] = __floats2half2_rn(v2, v3);
                s0 += v0 + v1; s1 += v2 + v3;
            } else {
                *(__half2*)&Ch[(size_t)row0    *N + col] = __floats2half2_rn(d[0]+b0, d[1]+b0);
                *(__half2*)&Ch[(size_t)(row0+8)*N + col] = __floats2half2_rn(d[2]+b1, d[3]+b1);
                if (MODE == 1) { s0 += d[0] + d[1] + 2.f*b0; s1 += d[2] + d[3] + 2.f*b1; }
            }
        }
        if (MODE == 1 || MODE == 2) {
            s0 += __shfl_xor_sync(0xffffffffu, s0, 1);
            s0 += __shfl_xor_sync(0xffffffffu, s0, 2);
            s1 += __shfl_xor_sync(0xffffffffu, s1, 1);
            s1 += __shfl_xor_sync(0xffffffffu, s1, 2);
            if (cq == 0) {
                atomicAdd(&raux1[(size_t)z * M + row0],     s0);
                atomicAdd(&raux1[(size_t)z * M + row0 + 8], s1);
            }
        }
    }
}

// ---------------- kernel: kmean x Qt -> p gate -> row scale ------------------
// rowmean[c] = mean_e' S[c,e'] = sum_e Qt[e,c] * kmean[e]   (exact identity)
__global__ void __launch_bounds__(512) pgate_kernel(const float* __restrict__ Wp,
                                                    const float* __restrict__ bp) {
    const int z = blockIdx.x;
    __shared__ float km[128];
    __shared__ float msh[512];
    const int tid = threadIdx.x;
    if (tid < 128) km[tid] = g_kmean[(size_t)z * 128 + tid] * (1.f/512.f);
    __syncthreads();

    const __half* Qz = g_Qth + (size_t)z * 65536;
    float rm = 0.f;
    #pragma unroll 4
    for (int e = 0; e < 128; e++)
        rm = fmaf(__half2float(Qz[(size_t)e * 512 + tid]), km[e], rm);
    msh[tid] = rm;
    __syncthreads();

    float accv = bp[tid];
    const float* wrow = Wp + (size_t)tid * 512;
    #pragma unroll 4
    for (int j = 0; j < 512; j++) accv = fmaf(msh[j], wrow[j], accv);
    float p = 1.f / (1.f + expf(-accv));
    g_rowscale[(size_t)z * 512 + tid] = exp2f(-7.f * (0.5f + p));   // D^{-(0.5+p)}
}

// ---------------- launch ----------------------------------------------------
extern "C" void kernel_launch(void* const* d_in, const int* in_sizes, int n_in,
                              void* d_out, int out_size) {
    const float* x   = (const float*)d_in[0];
    const float* Wqk = (const float*)d_in[1];
    const float* bqk = (const float*)d_in[2];
    const float* Wp  = (const float*)d_in[3];
    const float* bp  = (const float*)d_in[4];
    const float* Wv  = (const float*)d_in[5];
    const float* bv  = (const float*)d_in[6];
    const int*   wgt = (const int*)d_in[7];
    float* out = (float*)d_out;

    float *qpool, *kmean, *sumexp, *rowscale;
    __half *qpoolh, *kpoolh, *vpoolh, *Qth, *Kth, *Sh, *Wvh, *Wqkh;
    cudaGetSymbolAddress((void**)&qpool,    g_qpool);
    cudaGetSymbolAddress((void**)&qpoolh,   g_qpoolh);
    cudaGetSymbolAddress((void**)&kpoolh,   g_kpoolh);
    cudaGetSymbolAddress((void**)&vpoolh,   g_vpoolh);
    cudaGetSymbolAddress((void**)&Qth,      g_Qth);
    cudaGetSymbolAddress((void**)&Kth,      g_Kth);
    cudaGetSymbolAddress((void**)&Sh,       g_Sh);
    cudaGetSymbolAddress((void**)&Wvh,      g_Wvh);
    cudaGetSymbolAddress((void**)&Wqkh,     g_Wqkh);
    cudaGetSymbolAddress((void**)&kmean,    g_kmean);
    cudaGetSymbolAddress((void**)&sumexp,   g_sumexp);
    cudaGetSymbolAddress((void**)&rowscale, g_rowscale);

    cudaFuncSetAttribute(mm_f16<false,false,0>, cudaFuncAttributeMaxDynamicSharedMemorySize, 75776);
    cudaFuncSetAttribute(mm_f16<false,false,1>, cudaFuncAttributeMaxDynamicSharedMemorySize, 75776);
    cudaFuncSetAttribute(mm_f16<true, false,2>, cudaFuncAttributeMaxDynamicSharedMemorySize, 69632);
    cudaFuncSetAttribute(mm_f16<false,true, 3>, cudaFuncAttributeMaxDynamicSharedMemorySize, 81920);

    // 0) weight conversion to fp16; init reductions
    cvt_kernel<<<1024, 256>>>(Wv,  Wvh);    // 512*512
    cvt_kernel<<< 512, 256>>>(Wqk, Wqkh);   // 8*128*128
    init_kernel<<<256, 256>>>();

    // 1) fused avg/max pooling: x -> qpool(f32), qpool_h, kpool_h
    pool_kernel<<<8192, 256>>>(x);

    // 2) vpool_h[b] = Wv @ qpool[b] + bv   (1x1 conv & avgpool commute)
    mm_f16<false,false,0><<<dim3(8,4,16), 256, 75776>>>(
        Wvh, qpoolh, bv, vpoolh, 512, 1024, 512,
        1, 0, 524288, 524288, 1, 0, nullptr, nullptr, nullptr, nullptr);

    // 3) Kt[z] = Wqk[h] @ kpool_block[z] + bqk[h]  (+ fused row sums -> kmean)
    mm_f16<false,false,1><<<dim3(4,1,128), 256, 75776>>>(
        Wqkh, kpoolh, bqk, Kth, 128, 512, 128,
        8, 16384, 65536, 65536, 8, 128, kmean, nullptr, nullptr, nullptr);

    // 4) Qt[z] = Wqk[h] @ qpool_block[z] + bqk[h]
    mm_f16<false,false,0><<<dim3(4,1,128), 256, 75776>>>(
        Wqkh, qpoolh, bqk, Qth, 128, 512, 128,
        8, 16384, 65536, 65536, 8, 128, nullptr, nullptr, nullptr, nullptr);

    // 5) gate: rowmean = Qt . kmean -> sigmoid -> rowscale (before scores!)
    pgate_kernel<<<128, 512>>>(Wp, bp);

    // 6) S[z] = exp((Qt[z]^T @ Kt[z]) * rowscale) * 2^-4  (+ fused sumexp)
    //    (scores provably small; softmax shift-invariance makes no-max exact;
    //     2^-4 scaling keeps fp16 storage far from overflow and cancels below)
    mm_f16<true,false,2><<<dim3(4,4,128), 256, 69632>>>(
        Qth, Kth, nullptr, Sh, 512, 512, 128,
        1<<30, 65536, 65536, 262144, 1, 0, sumexp, rowscale, nullptr, nullptr);

    // 7) out[z] = qpool[z] + (V @ expS^T) * (1/sumexp) * (1+weight)
    mm_f16<false,true,3><<<dim3(4,1,128), 256, 81920>>>(
        vpoolh, Sh, nullptr, out, 128, 512, 512,
        1<<30, 65536, 262144, 65536, 1, 0, nullptr, sumexp, qpool, wgt);
}

// round 13
// speedup vs baseline: 3.0997x; 1.0019x over previous
#include <cuda_runtime.h>
#include <cuda_fp16.h>
#include <math.h>
#include <stdint.h>

// Problem constants
#define B_   16
#define C_   512
#define SP_  1024          // R*R
#define HN_  8
#define D_   128
#define NEG_INF -3.4e38f
// x is [16, 512, 96, 96]

// ---------------- scratch (static device arrays; no allocation) -------------
__device__ float  g_qpool [B_*C_*SP_];      // fp32, residual + attn resid input
__device__ __half g_qpoolh[B_*C_*SP_];      // fp16 GEMM operand
__device__ __half g_kpoolh[B_*C_*SP_];
__device__ __half g_vpoolh[B_*C_*SP_];
__device__ __half g_Qth[B_*HN_*D_*C_];      // [z][e*512 + c]
__device__ __half g_Kth[B_*HN_*D_*C_];
__device__ __half g_Sh [B_*HN_*C_*C_];      // exp(scaled scores)*2^-4, [z][c*512+e]
__device__ __half g_Wvh [C_*C_];
__device__ __half g_Wqkh[HN_*D_*D_];
__device__ float  g_kmean[B_*HN_*D_];       // row sums of Kt (over c), fp32
__device__ float  g_sumexp[B_*HN_*C_];      // per-(z,c) sum of exp*2^-4, fp32
__device__ float  g_rowscale[B_*HN_*C_];

// ---------------- helpers ----------------------------------------------------
__device__ __forceinline__ void mma_f16(float* d, const uint32_t* a, const uint32_t* b) {
    asm volatile("mma.sync.aligned.m16n8k16.row.col.f32.f16.f16.f32 "
        "{%0,%1,%2,%3}, {%4,%5,%6,%7}, {%8,%9}, {%0,%1,%2,%3};"
        : "+f"(d[0]), "+f"(d[1]), "+f"(d[2]), "+f"(d[3])
        : "r"(a[0]), "r"(a[1]), "r"(a[2]), "r"(a[3]), "r"(b[0]), "r"(b[1]));
}
__device__ __forceinline__ void ldsm4(uint32_t& r0, uint32_t& r1, uint32_t& r2, uint32_t& r3,
                                      uint32_t addr) {
    asm volatile("ldmatrix.sync.aligned.m8n8.x4.shared.b16 {%0,%1,%2,%3}, [%4];"
        : "=r"(r0), "=r"(r1), "=r"(r2), "=r"(r3) : "r"(addr));
}
__device__ __forceinline__ void ldsm4t(uint32_t& r0, uint32_t& r1, uint32_t& r2, uint32_t& r3,
                                       uint32_t addr) {
    asm volatile("ldmatrix.sync.aligned.m8n8.x4.trans.shared.b16 {%0,%1,%2,%3}, [%4];"
        : "=r"(r0), "=r"(r1), "=r"(r2), "=r"(r3) : "r"(addr));
}
__device__ __forceinline__ void cpa16(__half* dst, const __half* src) {
    uint32_t d = (uint32_t)__cvta_generic_to_shared(dst);
    asm volatile("cp.async.cg.shared.global [%0], [%1], 16;" :: "r"(d), "l"(src));
}

// ---------------- kernel 1: fused avg+max 3x3 pooling ----------------------
__global__ void __launch_bounds__(256) pool_kernel(const float* __restrict__ x) {
    __shared__ float tile[9216];
    const float4* s4 = reinterpret_cast<const float4*>(x + (size_t)blockIdx.x * 9216);
    float4* t4 = reinterpret_cast<float4*>(tile);
    #pragma unroll
    for (int i = 0; i < 9; i++)
        t4[threadIdx.x + i*256] = s4[threadIdx.x + i*256];
    __syncthreads();
    size_t base = (size_t)blockIdx.x * 1024;
    #pragma unroll
    for (int it = 0; it < 4; it++) {
        int sp = threadIdx.x + it*256;
        int r1 = sp >> 5, r2 = sp & 31;
        const float* p = &tile[r1*3*96 + r2*3];
        float s = 0.f, m = NEG_INF;
        #pragma unroll
        for (int i = 0; i < 3; i++)
            #pragma unroll
            for (int j = 0; j < 3; j++) {
                float v = p[i*96 + j];
                s += v;
                m = fmaxf(m, v);
            }
        float a = s * (1.f/9.f);
        g_qpool [base + sp] = a;
        g_qpoolh[base + sp] = __float2half_rn(a);
        g_kpoolh[base + sp] = __float2half_rn(m);
    }
}

// ---------------- init + weight conversion -----------------------------------
__global__ void init_kernel() {
    int i = blockIdx.x * 256 + threadIdx.x;
    g_sumexp[i] = 0.f;
    if (i < B_*HN_*D_) g_kmean[i] = 0.f;
}
__global__ void cvt_kernel(const float* __restrict__ src, __half* __restrict__ dst) {
    int i = blockIdx.x * 256 + threadIdx.x;
    dst[i] = __float2half_rn(src[i]);
}

// ---------------- fp16 tensor-core GEMM, 128x128 tile, K-chunk 32, 4 stages --
// MODE 0: C(h) = acc + bias
// MODE 1: C(h) = acc + bias, atomicAdd row sums into raux1[z*M+m]
// MODE 2: C(h) = exp(acc * raux2[z*M+m]) * 2^-4, atomicAdd row sums -> raux1
// MODE 3: C(f32) = resid + acc * (1/raux2[z*N+n]) * (1 + *wptr)
// smem layouts (fp16 units):
//   outer-major: 128 rows x 32 k, stride 40  (MK / NK)
//   k-major:      32 rows x 128,  stride 136 (KM / KN)
template<bool A_KM, bool B_NK, int MODE>
__global__ void __launch_bounds__(256) mm_f16(
    const __half* __restrict__ A, const __half* __restrict__ Bm,
    const float* __restrict__ bias, void* __restrict__ Cc,
    int M, int N, int K,
    int aMod, long long aStride, long long bStride, long long cStride,
    int biasMod, int biasStride,
    float* __restrict__ raux1, const float* __restrict__ raux2,
    const float* __restrict__ resid, const int* __restrict__ wptr)
{
    constexpr int STAGES = 4;
    constexpr int AW = A_KM ? 32*136 : 128*40;   // fp16 units per stage
    constexpr int BW = B_NK ? 128*40 : 32*136;
    extern __shared__ __half dsm[];
    __half* As = dsm;
    __half* Bs = dsm + STAGES*AW;
    __shared__ float sS[128];

    const int z = blockIdx.z;
    A  += (size_t)(z % aMod) * aStride;
    Bm += (size_t)z * bStride;

    const int bm = blockIdx.y * 128;
    const int bn = blockIdx.x * 128;
    const int tid  = threadIdx.x;
    const int lane = tid & 31;
    const int warp = tid >> 5;
    const int wm = warp >> 1;
    const int wn = warp & 1;
    const int qr = lane >> 2;
    const int cq = lane & 3;

    float acc[2][8][4];
    #pragma unroll
    for (int i = 0; i < 2; i++)
        #pragma unroll
        for (int j = 0; j < 8; j++)
            #pragma unroll
            for (int k = 0; k < 4; k++) acc[i][j][k] = 0.f;

    auto issue = [&](int t) {
        int buf = t & (STAGES-1);
        int k0 = t << 5;
        __half* Ab = As + buf*AW;
        __half* Bb = Bs + buf*BW;
        if (A_KM) {
            int k = tid >> 4, c = tid & 15;
            cpa16(Ab + k*136 + c*8,       A + (size_t)(k0+k)   *M + bm + c*8);
            cpa16(Ab + (k+16)*136 + c*8,  A + (size_t)(k0+k+16)*M + bm + c*8);
        } else {
            int m = tid >> 2, c = tid & 3;
            cpa16(Ab + m*40 + c*8,        A + (size_t)(bm+m)   *K + k0 + c*8);
            cpa16(Ab + (m+64)*40 + c*8,   A + (size_t)(bm+m+64)*K + k0 + c*8);
        }
        if (B_NK) {
            int n = tid >> 2, c = tid & 3;
            cpa16(Bb + n*40 + c*8,        Bm + (size_t)(bn+n)   *K + k0 + c*8);
            cpa16(Bb + (n+64)*40 + c*8,   Bm + (size_t)(bn+n+64)*K + k0 + c*8);
        } else {
            int k = tid >> 4, c = tid & 15;
            cpa16(Bb + k*136 + c*8,       Bm + (size_t)(k0+k)   *N + bn + c*8);
            cpa16(Bb + (k+16)*136 + c*8,  Bm + (size_t)(k0+k+16)*N + bn + c*8);
        }
        asm volatile("cp.async.commit_group;" ::: "memory");
    };

    const uint32_t aSm = (uint32_t)__cvta_generic_to_shared(As);
    const uint32_t bSm = (uint32_t)__cvta_generic_to_shared(Bs);

    auto compute = [&](int buf) {
        const uint32_t aBase = aSm + buf*AW*2;
        const uint32_t bBase = bSm + buf*BW*2;
        #pragma unroll
        for (int kk = 0; kk < 32; kk += 16) {
            uint32_t af[2][4], bf[8][2];
            #pragma unroll
            for (int mt = 0; mt < 2; mt++) {
                if (A_KM) {
                    uint32_t ad = aBase +
                        (((kk + (lane&7) + ((lane&16)>>1)) * 136) +
                          wm*32 + mt*16 + (lane&8)) * 2;
                    ldsm4t(af[mt][0], af[mt][1], af[mt][2], af[mt][3], ad);
                } else {
                    uint32_t ad = aBase +
                        (((wm*32 + mt*16 + (lane&15)) * 40) +
                          kk + ((lane&16)>>1)) * 2;
                    ldsm4(af[mt][0], af[mt][1], af[mt][2], af[mt][3], ad);
                }
            }
            #pragma unroll
            for (int j = 0; j < 4; j++) {
                if (B_NK) {
                    uint32_t bd = bBase +
                        (((wn*64 + j*16 + (lane&7) + ((lane&16)>>1)) * 40) +
                          kk + (lane&8)) * 2;
                    ldsm4(bf[2*j][0], bf[2*j][1], bf[2*j+1][0], bf[2*j+1][1], bd);
                } else {
                    uint32_t bd = bBase +
                        (((kk + (lane&7) + (lane&8)) * 136) +
                          wn*64 + j*16 + ((lane&16)>>1)) * 2;
                    ldsm4t(bf[2*j][0], bf[2*j][1], bf[2*j+1][0], bf[2*j+1][1], bd);
                }
            }
            #pragma unroll
            for (int mt = 0; mt < 2; mt++)
                #pragma unroll
                for (int nt = 0; nt < 8; nt++)
                    mma_f16(acc[mt][nt], af[mt], bf[nt]);
        }
    };

    // ---- pipelined main loop ----
    const int nT = K >> 5;
    #pragma unroll
    for (int s = 0; s < STAGES-1; s++) issue(s);
    if (MODE == 3 && tid < 128)
        sS[tid] = 1.f / raux2[(size_t)z * N + bn + tid];
    for (int t = 0; t < nT; t++) {
        asm volatile("cp.async.wait_group 2;" ::: "memory");
        __syncthreads();
        if (t + STAGES-1 < nT) issue(t + STAGES-1);
        else asm volatile("cp.async.commit_group;" ::: "memory");
        compute(t & (STAGES-1));
    }

    // ---- epilogue ----
    __half* Ch = (__half*)Cc + (MODE == 3 ? 0 : (size_t)z * cStride);
    float*  Cf = (float*)Cc + (size_t)z * cStride;
    const float* rz = (MODE == 3) ? resid + (size_t)z * cStride : nullptr;
    const float ws = (MODE == 3) ? (1.f + (float)wptr[0]) : 0.f;
    #pragma unroll
    for (int mt = 0; mt < 2; mt++) {
        int row0 = bm + wm*32 + mt*16 + qr;
        float b0 = 0.f, b1 = 0.f;
        if (MODE <= 1) {
            const float* bptr = bias + (size_t)(z % biasMod) * biasStride;
            b0 = bptr[row0]; b1 = bptr[row0 + 8];
        }
        float sc0 = 0.f, sc1 = 0.f;
        if (MODE == 2) {
            sc0 = raux2[(size_t)z * M + row0];
            sc1 = raux2[(size_t)z * M + row0 + 8];
        }
        float s0 = 0.f, s1 = 0.f;
        #pragma unroll
        for (int nt = 0; nt < 8; nt++) {
            int col = bn + wn*64 + nt*8 + cq*2;
            float* d = acc[mt][nt];
            if (MODE == 3) {
                int lc = wn*64 + nt*8 + cq*2;
                float i0 = sS[lc], i1 = sS[lc+1];
                float2 rv0 = *(const float2*)&rz[(size_t)row0    *N + col];
                float2 rv1 = *(const float2*)&rz[(size_t)(row0+8)*N + col];
                *(float2*)&Cf[(size_t)row0    *N + col] =
                    make_float2(rv0.x + d[0]*i0*ws, rv0.y + d[1]*i1*ws);
                *(float2*)&Cf[(size_t)(row0+8)*N + col] =
                    make_float2(rv1.x + d[2]*i0*ws, rv1.y + d[3]*i1*ws);
            } else if (MODE == 2) {
                float v0 = __expf(d[0]*sc0)*0.0625f, v1 = __expf(d[1]*sc0)*0.0625f;
                float v2 = __expf(d[2]*sc1)*0.0625f, v3 = __expf(d[3]*sc1)*0.0625f;
                *(__half2*)&Ch[(size_t)row0    *N + col] = __floats2half2_rn(v0, v1);
                *(__half2*)&Ch[(size_t)(row0+8)*N + col] = __floats2half2_rn(v2, v3);
                s0 += v0 + v1; s1 += v2 + v3;
            } else {
                *(__half2*)&Ch[(size_t)row0    *N + col] = __floats2half2_rn(d[0]+b0, d[1]+b0);
                *(__half2*)&Ch[(size_t)(row0+8)*N + col] = __floats2half2_rn(d[2]+b1, d[3]+b1);
                if (MODE == 1) { s0 += d[0] + d[1] + 2.f*b0; s1 += d[2] + d[3] + 2.f*b1; }
            }
        }
        if (MODE == 1 || MODE == 2) {
            s0 += __shfl_xor_sync(0xffffffffu, s0, 1);
            s0 += __shfl_xor_sync(0xffffffffu, s0, 2);
            s1 += __shfl_xor_sync(0xffffffffu, s1, 1);
            s1 += __shfl_xor_sync(0xffffffffu, s1, 2);
            if (cq == 0) {
                atomicAdd(&raux1[(size_t)z * M + row0],     s0);
                atomicAdd(&raux1[(size_t)z * M + row0 + 8], s1);
            }
        }
    }
}

// ---------------- kernel: kmean x Qt -> p gate -> row scale ------------------
// rowmean[c] = mean_e' S[c,e'] = sum_e Qt[e,c] * kmean[e]   (exact identity)
__global__ void __launch_bounds__(512) pgate_kernel(const float* __restrict__ Wp,
                                                    const float* __restrict__ bp) {
    const int z = blockIdx.x;
    __shared__ float km[128];
    __shared__ float msh[512];
    const int tid = threadIdx.x;
    if (tid < 128) km[tid] = g_kmean[(size_t)z * 128 + tid] * (1.f/512.f);
    __syncthreads();

    const __half* Qz = g_Qth + (size_t)z * 65536;
    float rm = 0.f;
    #pragma unroll 4
    for (int e = 0; e < 128; e++)
        rm = fmaf(__half2float(Qz[(size_t)e * 512 + tid]), km[e], rm);
    msh[tid] = rm;
    __syncthreads();

    float accv = bp[tid];
    const float* wrow = Wp + (size_t)tid * 512;
    #pragma unroll 4
    for (int j = 0; j < 512; j++) accv = fmaf(msh[j], wrow[j], accv);
    float p = 1.f / (1.f + expf(-accv));
    g_rowscale[(size_t)z * 512 + tid] = exp2f(-7.f * (0.5f + p));   // D^{-(0.5+p)}
}

// ---------------- launch ----------------------------------------------------
extern "C" void kernel_launch(void* const* d_in, const int* in_sizes, int n_in,
                              void* d_out, int out_size) {
    const float* x   = (const float*)d_in[0];
    const float* Wqk = (const float*)d_in[1];
    const float* bqk = (const float*)d_in[2];
    const float* Wp  = (const float*)d_in[3];
    const float* bp  = (const float*)d_in[4];
    const float* Wv  = (const float*)d_in[5];
    const float* bv  = (const float*)d_in[6];
    const int*   wgt = (const int*)d_in[7];
    float* out = (float*)d_out;

    float *qpool, *kmean, *sumexp, *rowscale;
    __half *qpoolh, *kpoolh, *vpoolh, *Qth, *Kth, *Sh, *Wvh, *Wqkh;
    cudaGetSymbolAddress((void**)&qpool,    g_qpool);
    cudaGetSymbolAddress((void**)&qpoolh,   g_qpoolh);
    cudaGetSymbolAddress((void**)&kpoolh,   g_kpoolh);
    cudaGetSymbolAddress((void**)&vpoolh,   g_vpoolh);
    cudaGetSymbolAddress((void**)&Qth,      g_Qth);
    cudaGetSymbolAddress((void**)&Kth,      g_Kth);
    cudaGetSymbolAddress((void**)&Sh,       g_Sh);
    cudaGetSymbolAddress((void**)&Wvh,      g_Wvh);
    cudaGetSymbolAddress((void**)&Wqkh,     g_Wqkh);
    cudaGetSymbolAddress((void**)&kmean,    g_kmean);
    cudaGetSymbolAddress((void**)&sumexp,   g_sumexp);
    cudaGetSymbolAddress((void**)&rowscale, g_rowscale);

    cudaFuncSetAttribute(mm_f16<false,false,0>, cudaFuncAttributeMaxDynamicSharedMemorySize, 75776);
    cudaFuncSetAttribute(mm_f16<false,false,1>, cudaFuncAttributeMaxDynamicSharedMemorySize, 75776);
    cudaFuncSetAttribute(mm_f16<true, false,2>, cudaFuncAttributeMaxDynamicSharedMemorySize, 69632);
    cudaFuncSetAttribute(mm_f16<false,true, 3>, cudaFuncAttributeMaxDynamicSharedMemorySize, 81920);

    // 0) weight conversion to fp16; init reductions
    cvt_kernel<<<1024, 256>>>(Wv,  Wvh);    // 512*512
    cvt_kernel<<< 512, 256>>>(Wqk, Wqkh);   // 8*128*128
    init_kernel<<<256, 256>>>();

    // 1) fused avg/max pooling: x -> qpool(f32), qpool_h, kpool_h
    pool_kernel<<<8192, 256>>>(x);

    // 2) vpool_h[b] = Wv @ qpool[b] + bv   (1x1 conv & avgpool commute)
    mm_f16<false,false,0><<<dim3(8,4,16), 256, 75776>>>(
        Wvh, qpoolh, bv, vpoolh, 512, 1024, 512,
        1, 0, 524288, 524288, 1, 0, nullptr, nullptr, nullptr, nullptr);

    // 3) Kt[z] = Wqk[h] @ kpool_block[z] + bqk[h]  (+ fused row sums -> kmean)
    mm_f16<false,false,1><<<dim3(4,1,128), 256, 75776>>>(
        Wqkh, kpoolh, bqk, Kth, 128, 512, 128,
        8, 16384, 65536, 65536, 8, 128, kmean, nullptr, nullptr, nullptr);

    // 4) Qt[z] = Wqk[h] @ qpool_block[z] + bqk[h]
    mm_f16<false,false,0><<<dim3(4,1,128), 256, 75776>>>(
        Wqkh, qpoolh, bqk, Qth, 128, 512, 128,
        8, 16384, 65536, 65536, 8, 128, nullptr, nullptr, nullptr, nullptr);

    // 5) gate: rowmean = Qt . kmean -> sigmoid -> rowscale (before scores!)
    pgate_kernel<<<128, 512>>>(Wp, bp);

    // 6) S[z] = exp((Qt[z]^T @ Kt[z]) * rowscale) * 2^-4  (+ fused sumexp)
    //    (scores provably small; softmax shift-invariance makes no-max exact;
    //     2^-4 scaling keeps fp16 storage far from overflow and cancels below)
    mm_f16<true,false,2><<<dim3(4,4,128), 256, 69632>>>(
        Qth, Kth, nullptr, Sh, 512, 512, 128,
        1<<30, 65536, 65536, 262144, 1, 0, sumexp, rowscale, nullptr, nullptr);

    // 7) out[z] = qpool[z] + (V @ expS^T) * (1/sumexp) * (1+weight)
    mm_f16<false,true,3><<<dim3(4,1,128), 256, 81920>>>(
        vpoolh, Sh, nullptr, out, 128, 512, 512,
        1<<30, 65536, 262144, 65536, 1, 0, nullptr, sumexp, qpool, wgt);
}